// round 2
// baseline (speedup 1.0000x reference)
#include <cuda_runtime.h>

#define NV 32
#define NT 8192
#define NL 16
#define NC (NV*NL)

// output region offsets (floats)
#define OFF_P  8388608u
#define OFF_MZ 25165824u
#define OFF_PZ 29360128u
#define OFF_LP 33554432u

#define F_JITTER 1e-6f
#define F_LOG2PI 1.8378770664093453f
#define SQRT3    1.7320508075688772f

__device__ double g_partial[NC];

// Build Matern-3/2 transition A(dt) and process noise Q(dt) (symmetric, 3 entries).
// A = e^{-x} [[1+x, dt],[-lam*x, 1-x]],  x = lam*dt
// Q00 = s2*(w^3/6 - w^4/8 + w^5/20 - w^6/72 + w^7/336), w = 2x   (stable series)
// Q01 = 2*s2*lam*x^2*e^2
// Q11 = s2*lam^2*(1 - e^2*(1 - w + w^2/2))
__device__ __forceinline__ void make_AQ(float dt, float lam, float s2,
    float &a11, float &a12, float &a21, float &a22,
    float &q00, float &q01, float &q11)
{
    float x  = lam * dt;
    float e  = expf(-x);
    a11 = e * (1.0f + x);
    a12 = e * dt;
    a21 = -e * lam * x;
    a22 = e * (1.0f - x);
    float w  = 2.0f * x;
    float e2 = e * e;
    float poly = 1.0f/6.0f + w*(-1.0f/8.0f + w*(1.0f/20.0f + w*(-1.0f/72.0f + w*(1.0f/336.0f))));
    q00 = s2 * w * w * w * poly;
    q01 = 2.0f * s2 * lam * x * x * e2;
    q11 = s2 * lam * lam * (1.0f - e2 * (1.0f - w + 0.5f*w*w));
}

// ---------------- forward Kalman filter: one thread per (v,l) chain ----------------
__global__ void __launch_bounds__(16, 1) filt_kernel(
    const float* __restrict__ dtn,   // (V, T-1)
    const float* __restrict__ ys,    // (V, T, L)
    const float* __restrict__ rs,    // (V, T, L)
    const float* __restrict__ ls,    // (L,)
    const float* __restrict__ vs,    // (L,)
    float* __restrict__ out)
{
    int c = blockIdx.x * blockDim.x + threadIdx.x;
    if (c >= NC) return;
    int v = c >> 4;
    int l = c & 15;

    float lam = SQRT3 / ls[l];
    float s2  = vs[l];

    // state
    float m0 = 0.0f, m1 = 0.0f;
    float p00 = s2, p01 = 0.0f, p11 = s2 * lam * lam;

    const float* dtp = dtn + (size_t)v * (NT - 1);
    const float* yp  = ys + (size_t)v * NT * NL + l;
    const float* rp  = rs + (size_t)v * NT * NL + l;
    float2* mo = reinterpret_cast<float2*>(out) + (size_t)c * NT;
    float4* po = reinterpret_cast<float4*>(out + OFF_P) + (size_t)c * NT;

    double acc = 0.0;

    #pragma unroll 4
    for (int t = 0; t < NT; ++t) {
        float dt = (t == 0) ? 0.0f : dtp[t - 1];
        float y  = yp[(size_t)t * NL];
        float r  = rp[(size_t)t * NL];

        float a11, a12, a21, a22, q00, q01, q11;
        make_AQ(dt, lam, s2, a11, a12, a21, a22, q00, q01, q11);

        // predict
        float mp0 = fmaf(a11, m0, a12 * m1);
        float mp1 = fmaf(a21, m0, a22 * m1);
        float t00 = fmaf(a11, p00, a12 * p01);
        float t01 = fmaf(a11, p01, a12 * p11);
        float t10 = fmaf(a21, p00, a22 * p01);
        float t11 = fmaf(a21, p01, a22 * p11);
        float Pp00 = fmaf(t00, a11, fmaf(t01, a12, q00));
        float Pp01 = fmaf(t00, a21, fmaf(t01, a22, q01));
        float Pp11 = fmaf(t10, a21, fmaf(t11, a22, q11));

        // update (H = [1,0], scalar obs)
        float s   = Pp00 + r;
        float d   = y - mp0;
        float inv = __fdividef(1.0f, s + F_JITTER);
        float w0  = Pp00 * inv;
        float w1  = Pp01 * inv;
        m0 = fmaf(w0, d, mp0);
        m1 = fmaf(w1, d, mp1);
        p00 = fmaf(-w0, Pp00, Pp00);
        p01 = fmaf(-w0, Pp01, Pp01);
        p11 = fmaf(-w1, Pp01, Pp11);

        // log-likelihood (off critical chain)
        float lp = -0.5f * (fmaf(d * d, __fdividef(1.0f, s), __logf(s)) + F_LOG2PI);
        acc += (double)lp;

        mo[t] = make_float2(m0, m1);
        po[t] = make_float4(p00, p01, p01, p11);
    }
    g_partial[c] = acc;
}

// ---------------- backward RTS smoother: one thread per (v,l) chain ----------------
__global__ void __launch_bounds__(16, 1) smooth_kernel(
    const float* __restrict__ dtn,
    const float* __restrict__ ls,
    const float* __restrict__ vs,
    float* __restrict__ out)
{
    int c = blockIdx.x * blockDim.x + threadIdx.x;
    if (c >= NC) return;
    int v = c >> 4;
    int l = c & 15;

    float lam = SQRT3 / ls[l];
    float s2  = vs[l];

    const float2* mi = reinterpret_cast<const float2*>(out) + (size_t)c * NT;
    const float4* pi = reinterpret_cast<const float4*>(out + OFF_P) + (size_t)c * NT;
    float* mz = out + OFF_MZ + (size_t)c * NT;
    float* pz = out + OFF_PZ + (size_t)c * NT;
    const float* dtp = dtn + (size_t)v * (NT - 1);

    // t = T-1: A_s = I, Q = 0  =>  smoothed == filtered (exact)
    float2 mf = mi[NT - 1];
    float4 pf = pi[NT - 1];
    float ms0 = mf.x, ms1 = mf.y;
    float sp00 = pf.x, sp01 = pf.y, sp11 = pf.w;
    mz[NT - 1] = ms0;
    pz[NT - 1] = sp00;

    #pragma unroll 4
    for (int t = NT - 2; t >= 0; --t) {
        mf = mi[t];
        pf = pi[t];
        float dt = dtp[t];   // A_s[t] = A(dt_nonzero[v,t])

        float a11, a12, a21, a22, q00, q01, q11;
        make_AQ(dt, lam, s2, a11, a12, a21, a22, q00, q01, q11);

        // predict from filtered state at t
        float mp0 = fmaf(a11, mf.x, a12 * mf.y);
        float mp1 = fmaf(a21, mf.x, a22 * mf.y);
        float t00 = fmaf(a11, pf.x, a12 * pf.y);   // A @ P_f
        float t01 = fmaf(a11, pf.y, a12 * pf.w);
        float t10 = fmaf(a21, pf.x, a22 * pf.y);
        float t11 = fmaf(a21, pf.y, a22 * pf.w);
        float Pp00 = fmaf(t00, a11, fmaf(t01, a12, q00));
        float Pp01 = fmaf(t00, a21, fmaf(t01, a22, q01));
        float Pp11 = fmaf(t10, a21, fmaf(t11, a22, q11));

        // G = (A P_f)^T (P_p + jitter I)^{-1}   (2x2 inverse via adjugate)
        float M00 = Pp00 + F_JITTER;
        float M11 = Pp11 + F_JITTER;
        float M01 = Pp01;
        float det = fmaf(M00, M11, -(M01 * M01));
        float di  = __fdividef(1.0f, det);
        float i00 =  M11 * di;
        float i01 = -M01 * di;
        float i11 =  M00 * di;
        float g00 = fmaf(t00, i00, t10 * i01);
        float g01 = fmaf(t00, i01, t10 * i11);
        float g10 = fmaf(t01, i00, t11 * i01);
        float g11 = fmaf(t01, i01, t11 * i11);

        // m_s = m_f + G (m_s - m_p)
        float dm0 = ms0 - mp0;
        float dm1 = ms1 - mp1;
        ms0 = mf.x + fmaf(g00, dm0, g01 * dm1);
        ms1 = mf.y + fmaf(g10, dm0, g11 * dm1);

        // P_s = P_f - G (P_s - P_p) G^T
        float d00 = sp00 - Pp00;
        float d01 = sp01 - Pp01;
        float d11 = sp11 - Pp11;
        float u00 = fmaf(g00, d00, g01 * d01);
        float u01 = fmaf(g00, d01, g01 * d11);
        float u10 = fmaf(g10, d00, g11 * d01);
        float u11 = fmaf(g10, d01, g11 * d11);
        sp00 = pf.x - fmaf(u00, g00, u01 * g01);
        sp01 = pf.y - fmaf(u00, g10, u01 * g11);
        sp11 = pf.w - fmaf(u10, g10, u11 * g11);

        mz[t] = ms0;
        pz[t] = sp00;
    }
}

// ---------------- deterministic log-lik reduction over L per v ----------------
__global__ void logp_kernel(float* __restrict__ out)
{
    int v = threadIdx.x;
    if (v < NV) {
        double s = 0.0;
        #pragma unroll
        for (int l = 0; l < NL; ++l) s += g_partial[v * NL + l];
        out[OFF_LP + v] = (float)s;
    }
}

extern "C" void kernel_launch(void* const* d_in, const int* in_sizes, int n_in,
                              void* d_out, int out_size)
{
    const float* dtn = (const float*)d_in[0];
    const float* ys  = (const float*)d_in[1];
    const float* rs  = (const float*)d_in[2];
    const float* ls  = (const float*)d_in[3];
    const float* vs  = (const float*)d_in[4];
    float* out = (float*)d_out;

    filt_kernel<<<NC / 16, 16>>>(dtn, ys, rs, ls, vs, out);
    smooth_kernel<<<NC / 16, 16>>>(dtn, ls, vs, out);
    logp_kernel<<<1, NV>>>(out);
}

// round 4
// speedup vs baseline: 1.3664x; 1.3664x over previous
#include <cuda_runtime.h>

#define NV 32
#define NT 8192
#define NT1 8191
#define NL 16
#define NC (NV*NL)

// output region offsets (floats)
#define OFF_P  8388608u
#define OFF_MZ 25165824u
#define OFF_PZ 29360128u
#define OFF_LP 33554432u

#define F_JITTER 1e-6f
#define F_LOG2PI 1.8378770664093453f
#define SQRT3    1.7320508075688772f

__device__ double g_partial[NC];
// Precomputed transition/process-noise tables: layout [v][tt][l], tt = 0..8190
// maps to dt = dt_nonzero[v][tt].
__device__ float4 g_tabA[NV * NT1 * NL];   // (a11, a12, a21, a22)
__device__ float4 g_tabQ[NV * NT1 * NL];   // (q00, q01, q11, 0)

// ---------------- precompute A(dt), Q(dt): fully parallel ----------------
// A = e^{-x} [[1+x, dt],[-lam*x, 1-x]],  x = lam*dt
// Q00 = s2*w^3*(1/6 - w/8 + w^2/20 - w^3/72 + w^4/336), w = 2x (stable series)
// Q01 = 2*s2*lam*x^2*e^2
// Q11 = s2*lam^2*(1 - e^2*(1 - w + w^2/2))
__global__ void prep_kernel(const float* __restrict__ dtn,
                            const float* __restrict__ ls,
                            const float* __restrict__ vs)
{
    int i = blockIdx.x * blockDim.x + threadIdx.x;
    if (i >= NV * NT1 * NL) return;
    int l  = i & 15;
    int vt = i >> 4;
    int v  = vt / NT1;
    int tt = vt - v * NT1;

    float dt  = dtn[(size_t)v * NT1 + tt];
    float lam = SQRT3 / ls[l];
    float s2  = vs[l];

    float x  = lam * dt;
    float e  = expf(-x);
    float a11 = e * (1.0f + x);
    float a12 = e * dt;
    float a21 = -e * lam * x;
    float a22 = e * (1.0f - x);
    float w  = 2.0f * x;
    float e2 = e * e;
    float poly = 1.0f/6.0f + w*(-1.0f/8.0f + w*(1.0f/20.0f + w*(-1.0f/72.0f + w*(1.0f/336.0f))));
    float q00 = s2 * w * w * w * poly;
    float q01 = 2.0f * s2 * lam * x * x * e2;
    float q11 = s2 * lam * lam * (1.0f - e2 * (1.0f - w + 0.5f*w*w));

    g_tabA[i] = make_float4(a11, a12, a21, a22);
    g_tabQ[i] = make_float4(q00, q01, q11, 0.0f);
}

// ---------------- filter step on register carry ----------------
struct FiltCarry { float m0, m1, p00, p01, p11; };

__device__ __forceinline__ float filt_step(FiltCarry& c, float4 A, float4 Q,
                                           float y, float r)
{
    float mp0 = fmaf(A.x, c.m0, A.y * c.m1);
    float mp1 = fmaf(A.z, c.m0, A.w * c.m1);
    float t00 = fmaf(A.x, c.p00, A.y * c.p01);
    float t01 = fmaf(A.x, c.p01, A.y * c.p11);
    float t10 = fmaf(A.z, c.p00, A.w * c.p01);
    float t11 = fmaf(A.z, c.p01, A.w * c.p11);
    float Pp00 = fmaf(t00, A.x, fmaf(t01, A.y, Q.x));
    float Pp01 = fmaf(t00, A.z, fmaf(t01, A.w, Q.y));
    float Pp11 = fmaf(t10, A.z, fmaf(t11, A.w, Q.z));

    float s   = Pp00 + r;
    float d   = y - mp0;
    float inv = __fdividef(1.0f, s + F_JITTER);
    float w0  = Pp00 * inv;
    float w1  = Pp01 * inv;
    c.m0  = fmaf(w0, d, mp0);
    c.m1  = fmaf(w1, d, mp1);
    c.p00 = fmaf(-w0, Pp00, Pp00);
    c.p01 = fmaf(-w0, Pp01, Pp01);
    c.p11 = fmaf(-w1, Pp01, Pp11);
    return -0.5f * (fmaf(d * d, __fdividef(1.0f, s), __logf(s)) + F_LOG2PI);
}

// ---------------- forward Kalman filter: one thread per (v,l) chain ----------------
__global__ void __launch_bounds__(16, 1) filt_kernel(
    const float* __restrict__ ys,    // (V, T, L)
    const float* __restrict__ rs,    // (V, T, L)
    const float* __restrict__ ls,    // (L,)
    const float* __restrict__ vs,    // (L,)
    float* __restrict__ out)
{
    int c = blockIdx.x * 16 + threadIdx.x;
    int v = c >> 4;
    int l = c & 15;

    float lam = SQRT3 / ls[l];
    float s2  = vs[l];

    const float*  yp = ys + (size_t)v * NT * NL + l;
    const float*  rp = rs + (size_t)v * NT * NL + l;
    const float4* tA = g_tabA + (size_t)v * NT1 * NL + l;
    const float4* tQ = g_tabQ + (size_t)v * NT1 * NL + l;
    float2* mo = reinterpret_cast<float2*>(out) + (size_t)c * NT;
    float4* po = reinterpret_cast<float4*>(out + OFF_P) + (size_t)c * NT;

    FiltCarry cr;
    double acc0 = 0.0, acc1 = 0.0, acc2 = 0.0, acc3 = 0.0;

    // t = 0 : dt = 0 -> A = I, Q = 0 -> m_p = 0, P_p = P0 = diag(s2, s2*lam^2)
    {
        float y = yp[0], r = rp[0];
        float s = s2 + r;
        float inv = __fdividef(1.0f, s + F_JITTER);
        float w0 = s2 * inv;
        cr.m0 = w0 * y;  cr.m1 = 0.0f;
        cr.p00 = s2 - w0 * s2;  cr.p01 = 0.0f;  cr.p11 = s2 * lam * lam;
        float lp = -0.5f * (fmaf(y * y, __fdividef(1.0f, s), __logf(s)) + F_LOG2PI);
        acc0 += (double)lp;
        mo[0] = make_float2(cr.m0, cr.m1);
        po[0] = make_float4(cr.p00, cr.p01, cr.p01, cr.p11);
    }

    // main: steps t = tt+1, tt = 0..8190.  1023 batches of 8 + tail of 7.
    int tt = 0;
    for (int b = 0; b < 1023; ++b, tt += 8) {
        float4 A[8], Q[8];
        float  yv[8], rv[8];
        #pragma unroll
        for (int j = 0; j < 8; ++j) {
            A[j]  = tA[(size_t)(tt + j) * NL];
            Q[j]  = tQ[(size_t)(tt + j) * NL];
            yv[j] = yp[(size_t)(tt + 1 + j) * NL];
            rv[j] = rp[(size_t)(tt + 1 + j) * NL];
        }
        #pragma unroll
        for (int j = 0; j < 8; ++j) {
            float lp = filt_step(cr, A[j], Q[j], yv[j], rv[j]);
            if ((j & 3) == 0) acc0 += (double)lp;
            else if ((j & 3) == 1) acc1 += (double)lp;
            else if ((j & 3) == 2) acc2 += (double)lp;
            else acc3 += (double)lp;
            int t = tt + 1 + j;
            mo[t] = make_float2(cr.m0, cr.m1);
            po[t] = make_float4(cr.p00, cr.p01, cr.p01, cr.p11);
        }
    }
    #pragma unroll
    for (int j = 0; j < 7; ++j) {
        int q = 8184 + j;
        float lp = filt_step(cr, tA[(size_t)q * NL], tQ[(size_t)q * NL],
                             yp[(size_t)(q + 1) * NL], rp[(size_t)(q + 1) * NL]);
        if ((j & 1) == 0) acc0 += (double)lp; else acc1 += (double)lp;
        mo[q + 1] = make_float2(cr.m0, cr.m1);
        po[q + 1] = make_float4(cr.p00, cr.p01, cr.p01, cr.p11);
    }

    g_partial[c] = (acc0 + acc1) + (acc2 + acc3);
}

// ---------------- smoother step on register carry ----------------
struct SmCarry { float ms0, ms1, sp00, sp01, sp11; };

__device__ __forceinline__ void sm_step(SmCarry& s, float2 mf, float4 pf,
                                        float4 A, float4 Q,
                                        float& mzv, float& pzv)
{
    float mp0 = fmaf(A.x, mf.x, A.y * mf.y);
    float mp1 = fmaf(A.z, mf.x, A.w * mf.y);
    float t00 = fmaf(A.x, pf.x, A.y * pf.y);   // A @ P_f
    float t01 = fmaf(A.x, pf.y, A.y * pf.w);
    float t10 = fmaf(A.z, pf.x, A.w * pf.y);
    float t11 = fmaf(A.z, pf.y, A.w * pf.w);
    float Pp00 = fmaf(t00, A.x, fmaf(t01, A.y, Q.x));
    float Pp01 = fmaf(t00, A.z, fmaf(t01, A.w, Q.y));
    float Pp11 = fmaf(t10, A.z, fmaf(t11, A.w, Q.z));

    // G = (A P_f)^T (P_p + jitter I)^{-1}
    float M00 = Pp00 + F_JITTER;
    float M11 = Pp11 + F_JITTER;
    float det = fmaf(M00, M11, -(Pp01 * Pp01));
    float di  = __fdividef(1.0f, det);
    float i00 =  M11 * di;
    float i01 = -Pp01 * di;
    float i11 =  M00 * di;
    float g00 = fmaf(t00, i00, t10 * i01);
    float g01 = fmaf(t00, i01, t10 * i11);
    float g10 = fmaf(t01, i00, t11 * i01);
    float g11 = fmaf(t01, i01, t11 * i11);

    float dm0 = s.ms0 - mp0;
    float dm1 = s.ms1 - mp1;
    s.ms0 = mf.x + fmaf(g00, dm0, g01 * dm1);
    s.ms1 = mf.y + fmaf(g10, dm0, g11 * dm1);

    float d00 = s.sp00 - Pp00;
    float d01 = s.sp01 - Pp01;
    float d11 = s.sp11 - Pp11;
    float u00 = fmaf(g00, d00, g01 * d01);
    float u01 = fmaf(g00, d01, g01 * d11);
    float u10 = fmaf(g10, d00, g11 * d01);
    float u11 = fmaf(g10, d01, g11 * d11);
    s.sp00 = pf.x - fmaf(u00, g00, u01 * g01);
    s.sp01 = pf.y - fmaf(u00, g10, u01 * g11);
    s.sp11 = pf.w - fmaf(u10, g10, u11 * g11);

    mzv = s.ms0;
    pzv = s.sp00;
}

// ---------------- backward RTS smoother: one thread per (v,l) chain ----------------
__global__ void __launch_bounds__(16, 1) smooth_kernel(float* __restrict__ out)
{
    int c = blockIdx.x * 16 + threadIdx.x;
    int v = c >> 4;
    int l = c & 15;

    const float2* mi = reinterpret_cast<const float2*>(out) + (size_t)c * NT;
    const float4* pi = reinterpret_cast<const float4*>(out + OFF_P) + (size_t)c * NT;
    const float4* tA = g_tabA + (size_t)v * NT1 * NL + l;
    const float4* tQ = g_tabQ + (size_t)v * NT1 * NL + l;
    float* mz = out + OFF_MZ + (size_t)c * NT;
    float* pz = out + OFF_PZ + (size_t)c * NT;

    // t = NT-1: A_s = I, Q = 0 => smoothed == filtered (exact)
    SmCarry s;
    {
        float2 mf = mi[NT - 1];
        float4 pf = pi[NT - 1];
        s.ms0 = mf.x; s.ms1 = mf.y;
        s.sp00 = pf.x; s.sp01 = pf.y; s.sp11 = pf.w;
        mz[NT - 1] = s.ms0;
        pz[NT - 1] = s.sp00;
    }

    // tail first: t = 8190 .. 8184 (7 steps), then 8-aligned batches t = 8183 .. 0
    #pragma unroll
    for (int j = 0; j < 7; ++j) {
        int t = 8190 - j;
        float mzv, pzv;
        sm_step(s, mi[t], pi[t], tA[(size_t)t * NL], tQ[(size_t)t * NL], mzv, pzv);
        mz[t] = mzv;
        pz[t] = pzv;
    }

    for (int tb = 8176; tb >= 0; tb -= 8) {
        float4 A[8], Q[8], pf[8];
        float2 mf[8];
        #pragma unroll
        for (int j = 0; j < 8; ++j) {
            int t = tb + j;
            A[j]  = tA[(size_t)t * NL];
            Q[j]  = tQ[(size_t)t * NL];
            mf[j] = mi[t];
            pf[j] = pi[t];
        }
        float mzv[8], pzv[8];
        #pragma unroll
        for (int j = 7; j >= 0; --j) {
            sm_step(s, mf[j], pf[j], A[j], Q[j], mzv[j], pzv[j]);
        }
        #pragma unroll
        for (int j = 0; j < 8; ++j) {
            mz[tb + j] = mzv[j];
            pz[tb + j] = pzv[j];
        }
    }
}

// ---------------- deterministic log-lik reduction over L per v ----------------
__global__ void logp_kernel(float* __restrict__ out)
{
    int v = threadIdx.x;
    if (v < NV) {
        double s = 0.0;
        #pragma unroll
        for (int l = 0; l < NL; ++l) s += g_partial[v * NL + l];
        out[OFF_LP + v] = (float)s;
    }
}

extern "C" void kernel_launch(void* const* d_in, const int* in_sizes, int n_in,
                              void* d_out, int out_size)
{
    const float* dtn = (const float*)d_in[0];
    const float* ys  = (const float*)d_in[1];
    const float* rs  = (const float*)d_in[2];
    const float* ls  = (const float*)d_in[3];
    const float* vs  = (const float*)d_in[4];
    float* out = (float*)d_out;

    prep_kernel<<<(NV * NT1 * NL + 255) / 256, 256>>>(dtn, ls, vs);
    filt_kernel<<<NC / 16, 16>>>(ys, rs, ls, vs, out);
    smooth_kernel<<<NC / 16, 16>>>(out);
    logp_kernel<<<1, NV>>>(out);
}

// round 6
// speedup vs baseline: 2.3137x; 1.6933x over previous
#include <cuda_runtime.h>

#define NV 32
#define NT 8192
#define NT1 8191
#define NL 16
#define NC 512

// output region offsets (floats)
#define OFF_P  8388608u
#define OFF_MZ 25165824u
#define OFF_PZ 29360128u
#define OFF_LP 33554432u

#define F_JITTER 1e-6f
#define F_LOG2PI 1.8378770664093453f
#define SQRT3    1.7320508075688772f

__device__ double g_partial[NC];
// filter transition tables [v][tt][l]
__device__ float4 g_tabA[NV * NT1 * NL];
__device__ float4 g_tabQ[NV * NT1 * NL];
// [t][c] transposed scratch (coalesced for the serial kernels)
__device__ float2 g_mscr[(size_t)NT * NC];   // filtered mean
__device__ float4 g_pscr[(size_t)NT * NC];   // filtered cov (p00,p01,p01,p11)
__device__ float4 g_gA[(size_t)NT1 * NC];    // smoother gain G
__device__ float4 g_gB[(size_t)NT1 * NC];    // (h0,h1,W00,W01)
__device__ float  g_gC[(size_t)NT1 * NC];    // W11
__device__ float  g_mzs[(size_t)NT * NC];    // smoothed mean (Z)
__device__ float  g_pzs[(size_t)NT * NC];    // smoothed var  (Z)

// ---------------- A(dt), Q(dt) ----------------
__device__ __forceinline__ void make_AQ(float dt, float lam, float s2,
    float &a11, float &a12, float &a21, float &a22,
    float &q00, float &q01, float &q11)
{
    float x  = lam * dt;
    float e  = expf(-x);
    a11 = e * (1.0f + x);
    a12 = e * dt;
    a21 = -e * lam * x;
    a22 = e * (1.0f - x);
    float w  = 2.0f * x;
    float e2 = e * e;
    float poly = 1.0f/6.0f + w*(-1.0f/8.0f + w*(1.0f/20.0f + w*(-1.0f/72.0f + w*(1.0f/336.0f))));
    q00 = s2 * w * w * w * poly;
    q01 = 2.0f * s2 * lam * x * x * e2;
    q11 = s2 * lam * lam * (1.0f - e2 * (1.0f - w + 0.5f*w*w));
}

// ---------------- precompute filter tables (parallel) ----------------
__global__ void prep_kernel(const float* __restrict__ dtn,
                            const float* __restrict__ ls,
                            const float* __restrict__ vs)
{
    int i = blockIdx.x * blockDim.x + threadIdx.x;
    if (i >= NV * NT1 * NL) return;
    int l  = i & 15;
    int vt = i >> 4;
    int v  = vt / NT1;
    int tt = vt - v * NT1;
    float dt  = dtn[(size_t)v * NT1 + tt];
    float lam = SQRT3 / ls[l];
    float s2  = vs[l];
    float a11,a12,a21,a22,q00,q01,q11;
    make_AQ(dt, lam, s2, a11,a12,a21,a22, q00,q01,q11);
    g_tabA[i] = make_float4(a11, a12, a21, a22);
    g_tabQ[i] = make_float4(q00, q01, q11, 0.0f);
}

// ---------------- filter step ----------------
struct FC { float m0, m1, p00, p01, p11; };

__device__ __forceinline__ float filt_step(FC& c, float4 A, float4 Q,
                                           float y, float r)
{
    float mp0 = fmaf(A.x, c.m0, A.y * c.m1);
    float mp1 = fmaf(A.z, c.m0, A.w * c.m1);
    float t00 = fmaf(A.x, c.p00, A.y * c.p01);
    float t01 = fmaf(A.x, c.p01, A.y * c.p11);
    float t10 = fmaf(A.z, c.p00, A.w * c.p01);
    float t11 = fmaf(A.z, c.p01, A.w * c.p11);
    float Pp00 = fmaf(t00, A.x, fmaf(t01, A.y, Q.x));
    float Pp01 = fmaf(t00, A.z, fmaf(t01, A.w, Q.y));
    float Pp11 = fmaf(t10, A.z, fmaf(t11, A.w, Q.z));

    float s   = Pp00 + r;
    float d   = y - mp0;
    float inv = __fdividef(1.0f, s + F_JITTER);
    float w0  = Pp00 * inv;
    float w1  = Pp01 * inv;
    c.m0  = fmaf(w0, d, mp0);
    c.m1  = fmaf(w1, d, mp1);
    c.p00 = fmaf(-w0, Pp00, Pp00);
    c.p01 = fmaf(-w0, Pp01, Pp01);
    c.p11 = fmaf(-w1, Pp01, Pp11);
    return -0.5f * (fmaf(d * d, __fdividef(1.0f, s), __logf(s)) + F_LOG2PI);
}

// ---------------- forward Kalman filter: coalesced scratch, pipelined ----------------
__global__ void __launch_bounds__(32, 1) filt_kernel(
    const float* __restrict__ ys,
    const float* __restrict__ rs,
    const float* __restrict__ ls,
    const float* __restrict__ vs)
{
    int lane = threadIdx.x;
    int c = blockIdx.x * 32 + lane;
    int v = c >> 4;
    int l = c & 15;

    float lam = SQRT3 / ls[l];
    float s2  = vs[l];

    const float*  yp = ys + (size_t)v * NT * NL + l;
    const float*  rp = rs + (size_t)v * NT * NL + l;
    const float4* tA = g_tabA + (size_t)v * NT1 * NL + l;
    const float4* tQ = g_tabQ + (size_t)v * NT1 * NL + l;

    FC cr;
    double accD = 0.0;

    // t = 0 : A = I, Q = 0 -> P_p = P0 = diag(s2, s2*lam^2)
    {
        float y = yp[0], r = rp[0];
        float s = s2 + r;
        float inv = __fdividef(1.0f, s + F_JITTER);
        float w0 = s2 * inv;
        cr.m0 = w0 * y;  cr.m1 = 0.0f;
        cr.p00 = s2 - w0 * s2;  cr.p01 = 0.0f;  cr.p11 = s2 * lam * lam;
        float lp = -0.5f * (fmaf(y * y, __fdividef(1.0f, s), __logf(s)) + F_LOG2PI);
        accD += (double)lp;
        g_mscr[c] = make_float2(cr.m0, cr.m1);
        g_pscr[c] = make_float4(cr.p00, cr.p01, cr.p01, cr.p11);
    }

    float4 A0[8], Q0[8], A1[8], Q1[8];
    float  y0[8], r0[8], y1[8], r1[8];

#define LOADB(Ab,Qb,yb,rb,tbase) { \
    _Pragma("unroll") \
    for (int j = 0; j < 8; ++j) { \
        int t = (tbase) + j; \
        Ab[j] = tA[(size_t)(t-1) * NL]; \
        Qb[j] = tQ[(size_t)(t-1) * NL]; \
        yb[j] = yp[(size_t)t * NL]; \
        rb[j] = rp[(size_t)t * NL]; \
    } }

#define COMP8(Ab,Qb,yb,rb,tbase) { \
    float s8 = 0.0f; \
    _Pragma("unroll") \
    for (int j = 0; j < 8; ++j) { \
        s8 += filt_step(cr, Ab[j], Qb[j], yb[j], rb[j]); \
        int t = (tbase) + j; \
        g_mscr[(size_t)t * NC + c] = make_float2(cr.m0, cr.m1); \
        g_pscr[(size_t)t * NC + c] = make_float4(cr.p00, cr.p01, cr.p01, cr.p11); \
    } \
    accD += (double)s8; }

    // steps t = 1 .. 8191 : 1023 batches of 8 (t=1..8184) + tail 7 (t=8185..8191)
    LOADB(A0, Q0, y0, r0, 1);
    for (int i = 0; i < 511; ++i) {
        LOADB(A1, Q1, y1, r1, 1 + 8*(2*i+1));
        COMP8(A0, Q0, y0, r0, 1 + 8*(2*i));
        LOADB(A0, Q0, y0, r0, 1 + 8*(2*i+2));
        COMP8(A1, Q1, y1, r1, 1 + 8*(2*i+1));
    }
    // tail loads t = 8185..8191 into buffer 1
    #pragma unroll
    for (int j = 0; j < 7; ++j) {
        int t = 8185 + j;
        A1[j] = tA[(size_t)(t-1) * NL];
        Q1[j] = tQ[(size_t)(t-1) * NL];
        y1[j] = yp[(size_t)t * NL];
        r1[j] = rp[(size_t)t * NL];
    }
    COMP8(A0, Q0, y0, r0, 8177);   // batch 1022
    {
        float s7 = 0.0f;
        #pragma unroll
        for (int j = 0; j < 7; ++j) {
            s7 += filt_step(cr, A1[j], Q1[j], y1[j], r1[j]);
            int t = 8185 + j;
            g_mscr[(size_t)t * NC + c] = make_float2(cr.m0, cr.m1);
            g_pscr[(size_t)t * NC + c] = make_float4(cr.p00, cr.p01, cr.p01, cr.p11);
        }
        accD += (double)s7;
    }
    g_partial[c] = accD;
#undef LOADB
#undef COMP8
}

// ---------------- gain precompute (fully parallel over (t, c)) ----------------
// For step t (0..8190): G, h = m_f - G m_p, W = P_f + G P_p G^T
__global__ void gain_kernel(const float* __restrict__ dtn,
                            const float* __restrict__ ls,
                            const float* __restrict__ vs)
{
    int idx = blockIdx.x * blockDim.x + threadIdx.x;
    if (idx >= NT1 * NC) return;
    int t = idx >> 9;
    int c = idx & 511;
    int v = c >> 4;
    int l = c & 15;

    float dt  = dtn[(size_t)v * NT1 + t];
    float lam = SQRT3 / ls[l];
    float s2  = vs[l];
    float a11,a12,a21,a22,q00,q01,q11;
    make_AQ(dt, lam, s2, a11,a12,a21,a22, q00,q01,q11);

    float2 mf = g_mscr[(size_t)t * NC + c];
    float4 pf = g_pscr[(size_t)t * NC + c];
    float pf00 = pf.x, pf01 = pf.y, pf11 = pf.w;

    float mp0 = fmaf(a11, mf.x, a12 * mf.y);
    float mp1 = fmaf(a21, mf.x, a22 * mf.y);
    float t00 = fmaf(a11, pf00, a12 * pf01);
    float t01 = fmaf(a11, pf01, a12 * pf11);
    float t10 = fmaf(a21, pf00, a22 * pf01);
    float t11 = fmaf(a21, pf01, a22 * pf11);
    float Pp00 = fmaf(t00, a11, fmaf(t01, a12, q00));
    float Pp01 = fmaf(t00, a21, fmaf(t01, a22, q01));
    float Pp11 = fmaf(t10, a21, fmaf(t11, a22, q11));

    float M00 = Pp00 + F_JITTER;
    float M11 = Pp11 + F_JITTER;
    float det = fmaf(M00, M11, -(Pp01 * Pp01));
    float di  = __fdividef(1.0f, det);
    float i00 =  M11 * di;
    float i01 = -Pp01 * di;
    float i11 =  M00 * di;
    float g00 = fmaf(t00, i00, t10 * i01);
    float g01 = fmaf(t00, i01, t10 * i11);
    float g10 = fmaf(t01, i00, t11 * i01);
    float g11 = fmaf(t01, i01, t11 * i11);

    float h0 = mf.x - fmaf(g00, mp0, g01 * mp1);
    float h1 = mf.y - fmaf(g10, mp0, g11 * mp1);

    // W = P_f + G P_p G^T
    float u00 = fmaf(g00, Pp00, g01 * Pp01);
    float u01 = fmaf(g00, Pp01, g01 * Pp11);
    float u10 = fmaf(g10, Pp00, g11 * Pp01);
    float u11 = fmaf(g10, Pp01, g11 * Pp11);
    float W00 = pf00 + fmaf(u00, g00, u01 * g01);
    float W01 = pf01 + fmaf(u00, g10, u01 * g11);
    float W11 = pf11 + fmaf(u10, g10, u11 * g11);

    g_gA[idx] = make_float4(g00, g01, g10, g11);
    g_gB[idx] = make_float4(h0, h1, W00, W01);
    g_gC[idx] = W11;
}

// ---------------- backward smoother: affine scan, coalesced, pipelined ----------------
__global__ void __launch_bounds__(32, 1) smooth_kernel()
{
    int lane = threadIdx.x;
    int c = blockIdx.x * 32 + lane;

    float ms0, ms1, s00, s01, s11;
    {
        float2 mf = g_mscr[(size_t)(NT-1) * NC + c];
        float4 pf = g_pscr[(size_t)(NT-1) * NC + c];
        ms0 = mf.x; ms1 = mf.y;
        s00 = pf.x; s01 = pf.y; s11 = pf.w;
        g_mzs[(size_t)(NT-1) * NC + c] = ms0;
        g_pzs[(size_t)(NT-1) * NC + c] = s00;
    }

    float4 GA0[8], GB0[8], GA1[8], GB1[8];
    float  GC0[8], GC1[8];

#define SLOAD(GAb,GBb,GCb,k) { \
    _Pragma("unroll") \
    for (int j = 0; j < 8; ++j) { \
        int t = 8190 - 8*(k) - j; \
        size_t ix = (size_t)t * NC + c; \
        GAb[j] = g_gA[ix]; GBb[j] = g_gB[ix]; GCb[j] = g_gC[ix]; \
    } }

#define SSTEP(G,B,Cw) { \
    float g00 = G.x, g01 = G.y, g10 = G.z, g11 = G.w; \
    float u00 = fmaf(g00, s00, g01 * s01); \
    float u01 = fmaf(g00, s01, g01 * s11); \
    float u10 = fmaf(g10, s00, g11 * s01); \
    float u11 = fmaf(g10, s01, g11 * s11); \
    float n0 = fmaf(g00, ms0, fmaf(g01, ms1, B.x)); \
    float n1 = fmaf(g10, ms0, fmaf(g11, ms1, B.y)); \
    s00 = B.z - fmaf(u00, g00, u01 * g01); \
    s01 = B.w - fmaf(u00, g10, u01 * g11); \
    s11 = (Cw) - fmaf(u10, g10, u11 * g11); \
    ms0 = n0; ms1 = n1; }

#define SCOMP8(GAb,GBb,GCb,k) { \
    _Pragma("unroll") \
    for (int j = 0; j < 8; ++j) { \
        SSTEP(GAb[j], GBb[j], GCb[j]); \
        int t = 8190 - 8*(k) - j; \
        size_t ix = (size_t)t * NC + c; \
        g_mzs[ix] = ms0; g_pzs[ix] = s00; \
    } }

    // steps t = 8190 .. 0 : 1023 batches of 8 (down to t=7) + tail 7 (t=6..0)
    SLOAD(GA0, GB0, GC0, 0);
    for (int i = 0; i < 511; ++i) {
        SLOAD(GA1, GB1, GC1, 2*i+1);
        SCOMP8(GA0, GB0, GC0, 2*i);
        SLOAD(GA0, GB0, GC0, 2*i+2);
        SCOMP8(GA1, GB1, GC1, 2*i+1);
    }
    #pragma unroll
    for (int j = 0; j < 7; ++j) {
        int t = 6 - j;
        size_t ix = (size_t)t * NC + c;
        GA1[j] = g_gA[ix]; GB1[j] = g_gB[ix]; GC1[j] = g_gC[ix];
    }
    SCOMP8(GA0, GB0, GC0, 1022);
    #pragma unroll
    for (int j = 0; j < 7; ++j) {
        SSTEP(GA1[j], GB1[j], GC1[j]);
        int t = 6 - j;
        size_t ix = (size_t)t * NC + c;
        g_mzs[ix] = ms0; g_pzs[ix] = s00;
    }
#undef SLOAD
#undef SSTEP
#undef SCOMP8
}

// ---------------- tiled transposes: [t][c] scratch -> [c][t] output ----------------
template <typename ET>
__device__ __forceinline__ void transpose_body(const ET* __restrict__ src,
                                               ET* __restrict__ dst)
{
    __shared__ ET tile[32][33];
    int tx = threadIdx.x, ty = threadIdx.y;
    int t0 = blockIdx.x * 32;
    int c0 = blockIdx.y * 32;
    #pragma unroll
    for (int j = ty; j < 32; j += 8)
        tile[j][tx] = src[(size_t)(t0 + j) * NC + c0 + tx];
    __syncthreads();
    #pragma unroll
    for (int j = ty; j < 32; j += 8)
        dst[(size_t)(c0 + j) * NT + t0 + tx] = tile[tx][j];
}

__global__ void tr_m_kernel(float* out)  { transpose_body<float2>(g_mscr, (float2*)out); }
__global__ void tr_p_kernel(float* out)  { transpose_body<float4>(g_pscr, (float4*)(out + OFF_P)); }
__global__ void tr_mz_kernel(float* out) { transpose_body<float>(g_mzs, out + OFF_MZ); }
__global__ void tr_pz_kernel(float* out) { transpose_body<float>(g_pzs, out + OFF_PZ); }

// ---------------- deterministic log-lik reduction ----------------
__global__ void logp_kernel(float* __restrict__ out)
{
    int v = threadIdx.x;
    if (v < NV) {
        double s = 0.0;
        #pragma unroll
        for (int l = 0; l < NL; ++l) s += g_partial[v * NL + l];
        out[OFF_LP + v] = (float)s;
    }
}

extern "C" void kernel_launch(void* const* d_in, const int* in_sizes, int n_in,
                              void* d_out, int out_size)
{
    const float* dtn = (const float*)d_in[0];
    const float* ys  = (const float*)d_in[1];
    const float* rs  = (const float*)d_in[2];
    const float* ls  = (const float*)d_in[3];
    const float* vs  = (const float*)d_in[4];
    float* out = (float*)d_out;

    dim3 trGrid(NT / 32, NC / 32);
    dim3 trBlk(32, 8);

    prep_kernel<<<(NV * NT1 * NL + 255) / 256, 256>>>(dtn, ls, vs);
    filt_kernel<<<NC / 32, 32>>>(ys, rs, ls, vs);
    gain_kernel<<<(NT1 * NC + 255) / 256, 256>>>(dtn, ls, vs);
    tr_m_kernel<<<trGrid, trBlk>>>(out);
    tr_p_kernel<<<trGrid, trBlk>>>(out);
    smooth_kernel<<<NC / 32, 32>>>();
    tr_mz_kernel<<<trGrid, trBlk>>>(out);
    tr_pz_kernel<<<trGrid, trBlk>>>(out);
    logp_kernel<<<1, NV>>>(out);
}

// round 7
// speedup vs baseline: 5.1682x; 2.2337x over previous
#include <cuda_runtime.h>

#define NV 32
#define NT 8192
#define NT1 8191
#define NL 16
#define NC 512

// output region offsets (floats)
#define OFF_P  8388608u
#define OFF_MZ 25165824u
#define OFF_PZ 29360128u
#define OFF_LP 33554432u

#define F_JITTER 1e-6f
#define F_LOG2PI 1.8378770664093453f
#define SQRT3    1.7320508075688772f

__device__ double g_partial[NC];
// filter transition tables, [t][c] layout (c fastest, coalesced)
__device__ float4 g_tabA[(size_t)NT1 * NC];
__device__ float4 g_tabQ[(size_t)NT1 * NC];
// [t][c] scratch
__device__ float2 g_mscr[(size_t)NT * NC];   // filtered mean
__device__ float4 g_pscr[(size_t)NT * NC];   // filtered cov
__device__ float4 g_gA[(size_t)NT1 * NC];    // smoother gain G
__device__ float4 g_gB[(size_t)NT1 * NC];    // (h0,h1,W00,W01)
__device__ float  g_gC[(size_t)NT1 * NC];    // W11
__device__ float  g_mzs[(size_t)NT * NC];    // smoothed mean (Z)
__device__ float  g_pzs[(size_t)NT * NC];    // smoothed var  (Z)

// ---------------- cp.async helpers ----------------
__device__ __forceinline__ void cp16(void* dst, const void* src) {
    unsigned d = (unsigned)__cvta_generic_to_shared(dst);
    asm volatile("cp.async.ca.shared.global [%0], [%1], 16;" :: "r"(d), "l"(src));
}
__device__ __forceinline__ void cp4(void* dst, const void* src) {
    unsigned d = (unsigned)__cvta_generic_to_shared(dst);
    asm volatile("cp.async.ca.shared.global [%0], [%1], 4;" :: "r"(d), "l"(src));
}
__device__ __forceinline__ void cp_commit() { asm volatile("cp.async.commit_group;"); }
__device__ __forceinline__ void cp_wait2()  { asm volatile("cp.async.wait_group 2;"); }

// ---------------- A(dt), Q(dt) ----------------
__device__ __forceinline__ void make_AQ(float dt, float lam, float s2,
    float &a11, float &a12, float &a21, float &a22,
    float &q00, float &q01, float &q11)
{
    float x  = lam * dt;
    float e  = expf(-x);
    a11 = e * (1.0f + x);
    a12 = e * dt;
    a21 = -e * lam * x;
    a22 = e * (1.0f - x);
    float w  = 2.0f * x;
    float e2 = e * e;
    float poly = 1.0f/6.0f + w*(-1.0f/8.0f + w*(1.0f/20.0f + w*(-1.0f/72.0f + w*(1.0f/336.0f))));
    q00 = s2 * w * w * w * poly;
    q01 = 2.0f * s2 * lam * x * x * e2;
    q11 = s2 * lam * lam * (1.0f - e2 * (1.0f - w + 0.5f*w*w));
}

// ---------------- precompute filter tables (parallel, [t][c]) ----------------
__global__ void prep_kernel(const float* __restrict__ dtn,
                            const float* __restrict__ ls,
                            const float* __restrict__ vs)
{
    int i = blockIdx.x * blockDim.x + threadIdx.x;
    if (i >= NT1 * NC) return;
    int t = i >> 9;
    int c = i & 511;
    int v = c >> 4;
    int l = c & 15;
    float dt  = dtn[(size_t)v * NT1 + t];
    float lam = SQRT3 / ls[l];
    float s2  = vs[l];
    float a11,a12,a21,a22,q00,q01,q11;
    make_AQ(dt, lam, s2, a11,a12,a21,a22, q00,q01,q11);
    g_tabA[i] = make_float4(a11, a12, a21, a22);
    g_tabQ[i] = make_float4(q00, q01, q11, 0.0f);
}

// ---------------- filter step: returns u = d^2*inv + log(s) ----------------
__device__ __forceinline__ float fstep(float &m0, float &m1,
                                       float &p00, float &p01, float &p11,
                                       float4 A, float4 Q, float y, float r)
{
    float mp0 = fmaf(A.x, m0, A.y * m1);
    float mp1 = fmaf(A.z, m0, A.w * m1);
    float t00 = fmaf(A.x, p00, A.y * p01);
    float t01 = fmaf(A.x, p01, A.y * p11);
    float t10 = fmaf(A.z, p00, A.w * p01);
    float t11 = fmaf(A.z, p01, A.w * p11);
    float Pp00 = fmaf(t00, A.x, fmaf(t01, A.y, Q.x));
    float Pp01 = fmaf(t00, A.z, fmaf(t01, A.w, Q.y));
    float Pp11 = fmaf(t10, A.z, fmaf(t11, A.w, Q.z));
    float s   = Pp00 + r;
    float d   = y - mp0;
    float inv = __fdividef(1.0f, s + F_JITTER);
    float w0  = Pp00 * inv;
    float w1  = Pp01 * inv;
    m0  = fmaf(w0, d, mp0);
    m1  = fmaf(w1, d, mp1);
    p00 = fmaf(-w0, Pp00, Pp00);
    p01 = fmaf(-w0, Pp01, Pp01);
    p11 = fmaf(-w1, Pp01, Pp11);
    return fmaf(d * d, inv, __logf(s));
}

// ---------------- forward filter: producer/consumer pipelined ----------------
__global__ void __launch_bounds__(64, 1) filt_kernel(
    const float* __restrict__ ys,
    const float* __restrict__ rs,
    const float* __restrict__ ls,
    const float* __restrict__ vs)
{
    __shared__ float4 sA[4][8][32];
    __shared__ float4 sQ[4][8][32];
    __shared__ float  sy[4][8][32];
    __shared__ float  sr[4][8][32];

    int lane = threadIdx.x & 31;
    int wid  = threadIdx.x >> 5;
    int c = blockIdx.x * 32 + lane;
    int v = c >> 4;
    int l = c & 15;
    const float* yp = ys + (size_t)v * NT * NL + l;
    const float* rp = rs + (size_t)v * NT * NL + l;

#define PRODF(s_) { int slot_ = (s_) & 3; int tb_ = 1 + 8 * (s_); \
    _Pragma("unroll") \
    for (int j = 0; j < 8; ++j) { int t_ = tb_ + j; \
        cp16(&sA[slot_][j][lane], g_tabA + (size_t)(t_ - 1) * NC + c); \
        cp16(&sQ[slot_][j][lane], g_tabQ + (size_t)(t_ - 1) * NC + c); \
        cp4 (&sy[slot_][j][lane], yp + (size_t)t_ * NL); \
        cp4 (&sr[slot_][j][lane], rp + (size_t)t_ * NL); } \
    cp_commit(); }

    if (wid == 1) {
        // ---- producer ----
        PRODF(0); PRODF(1); PRODF(2);
        cp_wait2();
        __syncthreads();
        for (int i = 0; i < 1023; ++i) {
            if (i + 3 < 1023) { PRODF(i + 3); } else { cp_commit(); }
            cp_wait2();
            __syncthreads();
        }
    } else {
        // ---- consumer ----
        float lam = SQRT3 / ls[l];
        float s2  = vs[l];
        float m0, m1, p00, p01, p11;
        double accD = 0.0;
        {   // t = 0 : A = I, Q = 0 -> P_p = P0 = diag(s2, s2*lam^2)
            float y = yp[0], r = rp[0];
            float s = s2 + r;
            float inv = __fdividef(1.0f, s + F_JITTER);
            float w0 = s2 * inv;
            m0 = w0 * y;  m1 = 0.0f;
            p00 = s2 - w0 * s2;  p01 = 0.0f;  p11 = s2 * lam * lam;
            accD += (double)fmaf(y * y, inv, __logf(s));
            g_mscr[c] = make_float2(m0, m1);
            g_pscr[c] = make_float4(p00, p01, p01, p11);
        }
        __syncthreads();
        for (int i = 0; i < 1023; ++i) {
            int slot = i & 3;
            int tb = 1 + 8 * i;
            float acc8 = 0.0f;
            #pragma unroll
            for (int j = 0; j < 8; ++j) {
                float4 A = sA[slot][j][lane];
                float4 Q = sQ[slot][j][lane];
                float y  = sy[slot][j][lane];
                float r  = sr[slot][j][lane];
                acc8 += fstep(m0, m1, p00, p01, p11, A, Q, y, r);
                size_t ix = (size_t)(tb + j) * NC + c;
                g_mscr[ix] = make_float2(m0, m1);
                g_pscr[ix] = make_float4(p00, p01, p01, p11);
            }
            accD += (double)acc8;
            __syncthreads();
        }
        // tail t = 8185..8191 (direct loads, one-time latency)
        float acc7 = 0.0f;
        #pragma unroll
        for (int j = 0; j < 7; ++j) {
            int t = 8185 + j;
            float4 A = g_tabA[(size_t)(t - 1) * NC + c];
            float4 Q = g_tabQ[(size_t)(t - 1) * NC + c];
            float y = yp[(size_t)t * NL];
            float r = rp[(size_t)t * NL];
            acc7 += fstep(m0, m1, p00, p01, p11, A, Q, y, r);
            size_t ix = (size_t)t * NC + c;
            g_mscr[ix] = make_float2(m0, m1);
            g_pscr[ix] = make_float4(p00, p01, p01, p11);
        }
        accD += (double)acc7;
        g_partial[c] = -0.5 * (accD + (double)NT * (double)F_LOG2PI);
    }
#undef PRODF
}

// ---------------- gain precompute (fully parallel over (t, c)) ----------------
__global__ void gain_kernel(const float* __restrict__ dtn,
                            const float* __restrict__ ls,
                            const float* __restrict__ vs)
{
    int idx = blockIdx.x * blockDim.x + threadIdx.x;
    if (idx >= NT1 * NC) return;
    int t = idx >> 9;
    int c = idx & 511;
    int v = c >> 4;
    int l = c & 15;

    float dt  = dtn[(size_t)v * NT1 + t];
    float lam = SQRT3 / ls[l];
    float s2  = vs[l];
    float a11,a12,a21,a22,q00,q01,q11;
    make_AQ(dt, lam, s2, a11,a12,a21,a22, q00,q01,q11);

    float2 mf = g_mscr[(size_t)t * NC + c];
    float4 pf = g_pscr[(size_t)t * NC + c];
    float pf00 = pf.x, pf01 = pf.y, pf11 = pf.w;

    float mp0 = fmaf(a11, mf.x, a12 * mf.y);
    float mp1 = fmaf(a21, mf.x, a22 * mf.y);
    float t00 = fmaf(a11, pf00, a12 * pf01);
    float t01 = fmaf(a11, pf01, a12 * pf11);
    float t10 = fmaf(a21, pf00, a22 * pf01);
    float t11 = fmaf(a21, pf01, a22 * pf11);
    float Pp00 = fmaf(t00, a11, fmaf(t01, a12, q00));
    float Pp01 = fmaf(t00, a21, fmaf(t01, a22, q01));
    float Pp11 = fmaf(t10, a21, fmaf(t11, a22, q11));

    float M00 = Pp00 + F_JITTER;
    float M11 = Pp11 + F_JITTER;
    float det = fmaf(M00, M11, -(Pp01 * Pp01));
    float di  = __fdividef(1.0f, det);
    float i00 =  M11 * di;
    float i01 = -Pp01 * di;
    float i11 =  M00 * di;
    float g00 = fmaf(t00, i00, t10 * i01);
    float g01 = fmaf(t00, i01, t10 * i11);
    float g10 = fmaf(t01, i00, t11 * i01);
    float g11 = fmaf(t01, i01, t11 * i11);

    float h0 = mf.x - fmaf(g00, mp0, g01 * mp1);
    float h1 = mf.y - fmaf(g10, mp0, g11 * mp1);

    float u00 = fmaf(g00, Pp00, g01 * Pp01);
    float u01 = fmaf(g00, Pp01, g01 * Pp11);
    float u10 = fmaf(g10, Pp00, g11 * Pp01);
    float u11 = fmaf(g10, Pp01, g11 * Pp11);
    float W00 = pf00 + fmaf(u00, g00, u01 * g01);
    float W01 = pf01 + fmaf(u00, g10, u01 * g11);
    float W11 = pf11 + fmaf(u10, g10, u11 * g11);

    g_gA[idx] = make_float4(g00, g01, g10, g11);
    g_gB[idx] = make_float4(h0, h1, W00, W01);
    g_gC[idx] = W11;
}

// ---------------- backward smoother: producer/consumer pipelined ----------------
__global__ void __launch_bounds__(64, 1) smooth_kernel()
{
    __shared__ float4 sG[4][8][32];
    __shared__ float4 sB[4][8][32];
    __shared__ float  sC[4][8][32];

    int lane = threadIdx.x & 31;
    int wid  = threadIdx.x >> 5;
    int c = blockIdx.x * 32 + lane;

#define PRODS(s_) { int slot_ = (s_) & 3; int tb_ = 8190 - 8 * (s_); \
    _Pragma("unroll") \
    for (int j = 0; j < 8; ++j) { int t_ = tb_ - j; \
        cp16(&sG[slot_][j][lane], g_gA + (size_t)t_ * NC + c); \
        cp16(&sB[slot_][j][lane], g_gB + (size_t)t_ * NC + c); \
        cp4 (&sC[slot_][j][lane], g_gC + (size_t)t_ * NC + c); } \
    cp_commit(); }

#define SSTEP(G,B,Cw) { \
    float g00 = G.x, g01 = G.y, g10 = G.z, g11 = G.w; \
    float u00 = fmaf(g00, s00, g01 * s01); \
    float u01 = fmaf(g00, s01, g01 * s11); \
    float u10 = fmaf(g10, s00, g11 * s01); \
    float u11 = fmaf(g10, s01, g11 * s11); \
    float n0 = fmaf(g00, ms0, fmaf(g01, ms1, B.x)); \
    float n1 = fmaf(g10, ms0, fmaf(g11, ms1, B.y)); \
    s00 = B.z - fmaf(u00, g00, u01 * g01); \
    s01 = B.w - fmaf(u00, g10, u01 * g11); \
    s11 = (Cw) - fmaf(u10, g10, u11 * g11); \
    ms0 = n0; ms1 = n1; }

    if (wid == 1) {
        PRODS(0); PRODS(1); PRODS(2);
        cp_wait2();
        __syncthreads();
        for (int i = 0; i < 1023; ++i) {
            if (i + 3 < 1023) { PRODS(i + 3); } else { cp_commit(); }
            cp_wait2();
            __syncthreads();
        }
    } else {
        float ms0, ms1, s00, s01, s11;
        {   // t = NT-1 : smoothed == filtered
            float2 mf = g_mscr[(size_t)(NT-1) * NC + c];
            float4 pf = g_pscr[(size_t)(NT-1) * NC + c];
            ms0 = mf.x; ms1 = mf.y;
            s00 = pf.x; s01 = pf.y; s11 = pf.w;
            g_mzs[(size_t)(NT-1) * NC + c] = ms0;
            g_pzs[(size_t)(NT-1) * NC + c] = s00;
        }
        __syncthreads();
        for (int i = 0; i < 1023; ++i) {
            int slot = i & 3;
            int tb = 8190 - 8 * i;
            #pragma unroll
            for (int j = 0; j < 8; ++j) {
                float4 G = sG[slot][j][lane];
                float4 B = sB[slot][j][lane];
                float Cw = sC[slot][j][lane];
                SSTEP(G, B, Cw);
                size_t ix = (size_t)(tb - j) * NC + c;
                g_mzs[ix] = ms0;
                g_pzs[ix] = s00;
            }
            __syncthreads();
        }
        // tail t = 6..0
        #pragma unroll
        for (int j = 0; j < 7; ++j) {
            int t = 6 - j;
            size_t ix = (size_t)t * NC + c;
            float4 G = g_gA[ix];
            float4 B = g_gB[ix];
            float Cw = g_gC[ix];
            SSTEP(G, B, Cw);
            g_mzs[ix] = ms0;
            g_pzs[ix] = s00;
        }
    }
#undef PRODS
#undef SSTEP
}

// ---------------- tiled transposes: [t][c] scratch -> [c][t] output ----------------
template <typename ET>
__device__ __forceinline__ void transpose_body(const ET* __restrict__ src,
                                               ET* __restrict__ dst)
{
    __shared__ ET tile[32][33];
    int tx = threadIdx.x, ty = threadIdx.y;
    int t0 = blockIdx.x * 32;
    int c0 = blockIdx.y * 32;
    #pragma unroll
    for (int j = ty; j < 32; j += 8)
        tile[j][tx] = src[(size_t)(t0 + j) * NC + c0 + tx];
    __syncthreads();
    #pragma unroll
    for (int j = ty; j < 32; j += 8)
        dst[(size_t)(c0 + j) * NT + t0 + tx] = tile[tx][j];
}

__global__ void tr_m_kernel(float* out)  { transpose_body<float2>(g_mscr, (float2*)out); }
__global__ void tr_p_kernel(float* out)  { transpose_body<float4>(g_pscr, (float4*)(out + OFF_P)); }
__global__ void tr_mz_kernel(float* out) { transpose_body<float>(g_mzs, out + OFF_MZ); }
__global__ void tr_pz_kernel(float* out) { transpose_body<float>(g_pzs, out + OFF_PZ); }

// ---------------- deterministic log-lik reduction ----------------
__global__ void logp_kernel(float* __restrict__ out)
{
    int v = threadIdx.x;
    if (v < NV) {
        double s = 0.0;
        #pragma unroll
        for (int l = 0; l < NL; ++l) s += g_partial[v * NL + l];
        out[OFF_LP + v] = (float)s;
    }
}

extern "C" void kernel_launch(void* const* d_in, const int* in_sizes, int n_in,
                              void* d_out, int out_size)
{
    const float* dtn = (const float*)d_in[0];
    const float* ys  = (const float*)d_in[1];
    const float* rs  = (const float*)d_in[2];
    const float* ls  = (const float*)d_in[3];
    const float* vs  = (const float*)d_in[4];
    float* out = (float*)d_out;

    dim3 trGrid(NT / 32, NC / 32);
    dim3 trBlk(32, 8);

    prep_kernel<<<(NT1 * NC + 255) / 256, 256>>>(dtn, ls, vs);
    filt_kernel<<<NC / 32, 64>>>(ys, rs, ls, vs);
    gain_kernel<<<(NT1 * NC + 255) / 256, 256>>>(dtn, ls, vs);
    tr_m_kernel<<<trGrid, trBlk>>>(out);
    tr_p_kernel<<<trGrid, trBlk>>>(out);
    smooth_kernel<<<NC / 32, 64>>>();
    tr_mz_kernel<<<trGrid, trBlk>>>(out);
    tr_pz_kernel<<<trGrid, trBlk>>>(out);
    logp_kernel<<<1, NV>>>(out);
}

// round 8
// speedup vs baseline: 7.9676x; 1.5417x over previous
#include <cuda_runtime.h>

#define NV 32
#define NT 8192
#define NT1 8191
#define NL 16
#define NC 512
#define NKF 256    /* filter chunks of 32 steps  */
#define CHF 32
#define NKS 512    /* smoother chunks of 16 steps */
#define CHS 16

#define OFF_P  8388608u
#define OFF_MZ 25165824u
#define OFF_PZ 29360128u
#define OFF_LP 33554432u

#define F_JITTER 1e-6f
#define F_LOG2PI 1.8378770664093453f
#define SQRT3    1.7320508075688772f

// [t][c] scratch
__device__ float2 g_mscr[(size_t)NT * NC];
__device__ float4 g_pscr[(size_t)NT * NC];
__device__ float  g_mzs[(size_t)NT * NC];
__device__ float  g_pzs[(size_t)NT * NC];
__device__ float  g_lpp[NKF * NC];
// filter chunk composites (A, b, C, eta, J)
__device__ float4 g_feA[NKF * NC];   // A00,A01,A10,A11
__device__ float4 g_feB[NKF * NC];   // b0,b1,eta0,eta1
__device__ float4 g_feC[NKF * NC];   // C00,C01,C11,J00
__device__ float2 g_feJ[NKF * NC];   // J01,J11
// filter chunk boundary states (state at chunk start)
__device__ float2 g_fbM[NKF * NC];
__device__ float4 g_fbP[NKF * NC];
// smoother chunk composites: m' = M m + v ; Pvec' = L Pvec + w
__device__ float4 g_seM[NKS * NC];   // M00,M01,M10,M11
__device__ float4 g_seV[NKS * NC];   // v0,v1,w0,w1
__device__ float4 g_seL1[NKS * NC];  // L00,L01,L02,L10
__device__ float4 g_seL2[NKS * NC];  // L11,L12,L20,L21
__device__ float2 g_seL3[NKS * NC];  // L22, w2
// smoother boundaries (state at chunk-end+1)
__device__ float2 g_sbM[NKS * NC];
__device__ float4 g_sbP[NKS * NC];

// ---------------- A(dt), Q(dt) ----------------
__device__ __forceinline__ void make_AQ(float dt, float lam, float s2,
    float &a11, float &a12, float &a21, float &a22,
    float &q00, float &q01, float &q11)
{
    float x  = lam * dt;
    float e  = expf(-x);
    a11 = e * (1.0f + x);
    a12 = e * dt;
    a21 = -e * lam * x;
    a22 = e * (1.0f - x);
    float w  = 2.0f * x;
    float e2 = e * e;
    float poly = 1.0f/6.0f + w*(-1.0f/8.0f + w*(1.0f/20.0f + w*(-1.0f/72.0f + w*(1.0f/336.0f))));
    q00 = s2 * w * w * w * poly;
    q01 = 2.0f * s2 * lam * x * x * e2;
    q11 = s2 * lam * lam * (1.0f - e2 * (1.0f - w + 0.5f*w*w));
}

// ---------------- exact filter step (jittered gain, matches reference) ----------------
__device__ __forceinline__ float fstep(float &m0, float &m1,
                                       float &p00, float &p01, float &p11,
                                       float a11, float a12, float a21, float a22,
                                       float q00, float q01, float q11,
                                       float y, float r)
{
    float mp0 = fmaf(a11, m0, a12 * m1);
    float mp1 = fmaf(a21, m0, a22 * m1);
    float t00 = fmaf(a11, p00, a12 * p01);
    float t01 = fmaf(a11, p01, a12 * p11);
    float t10 = fmaf(a21, p00, a22 * p01);
    float t11 = fmaf(a21, p01, a22 * p11);
    float Pp00 = fmaf(t00, a11, fmaf(t01, a12, q00));
    float Pp01 = fmaf(t00, a21, fmaf(t01, a22, q01));
    float Pp11 = fmaf(t10, a21, fmaf(t11, a22, q11));
    float s   = Pp00 + r;
    float d   = y - mp0;
    float inv = __fdividef(1.0f, s + F_JITTER);
    float w0  = Pp00 * inv;
    float w1  = Pp01 * inv;
    m0  = fmaf(w0, d, mp0);
    m1  = fmaf(w1, d, mp1);
    p00 = fmaf(-w0, Pp00, Pp00);
    p01 = fmaf(-w0, Pp01, Pp01);
    p11 = fmaf(-w1, Pp01, Pp11);
    return fmaf(d * d, inv, __logf(s));
}

// ---------------- smoother gain quantities (matches validated gain_kernel) ----------------
__device__ __forceinline__ void sgain(float mf0, float mf1,
                                      float pf00, float pf01, float pf11,
                                      float a11, float a12, float a21, float a22,
                                      float q00, float q01, float q11,
                                      float &g00, float &g01, float &g10, float &g11,
                                      float &h0, float &h1,
                                      float &W00, float &W01, float &W11)
{
    float mp0 = fmaf(a11, mf0, a12 * mf1);
    float mp1 = fmaf(a21, mf0, a22 * mf1);
    float t00 = fmaf(a11, pf00, a12 * pf01);
    float t01 = fmaf(a11, pf01, a12 * pf11);
    float t10 = fmaf(a21, pf00, a22 * pf01);
    float t11 = fmaf(a21, pf01, a22 * pf11);
    float Pp00 = fmaf(t00, a11, fmaf(t01, a12, q00));
    float Pp01 = fmaf(t00, a21, fmaf(t01, a22, q01));
    float Pp11 = fmaf(t10, a21, fmaf(t11, a22, q11));
    float M00 = Pp00 + F_JITTER;
    float M11 = Pp11 + F_JITTER;
    float det = fmaf(M00, M11, -(Pp01 * Pp01));
    float di  = __fdividef(1.0f, det);
    float i00 =  M11 * di;
    float i01 = -Pp01 * di;
    float i11 =  M00 * di;
    g00 = fmaf(t00, i00, t10 * i01);
    g01 = fmaf(t00, i01, t10 * i11);
    g10 = fmaf(t01, i00, t11 * i01);
    g11 = fmaf(t01, i01, t11 * i11);
    h0 = mf0 - fmaf(g00, mp0, g01 * mp1);
    h1 = mf1 - fmaf(g10, mp0, g11 * mp1);
    float u00 = fmaf(g00, Pp00, g01 * Pp01);
    float u01 = fmaf(g00, Pp01, g01 * Pp11);
    float u10 = fmaf(g10, Pp00, g11 * Pp01);
    float u11 = fmaf(g10, Pp01, g11 * Pp11);
    W00 = pf00 + fmaf(u00, g00, u01 * g01);
    W01 = pf01 + fmaf(u00, g10, u01 * g11);
    W11 = pf11 + fmaf(u10, g10, u11 * g11);
}

// ================= F2: filter chunk composites =================
__global__ void __launch_bounds__(512) fscan_chunk(
    const float* __restrict__ dtn,
    const float* __restrict__ ys,
    const float* __restrict__ rs,
    const float* __restrict__ ls,
    const float* __restrict__ vs)
{
    int c = threadIdx.x;
    int k = blockIdx.x;
    int v = c >> 4, l = c & 15;
    float lam = SQRT3 / ls[l];
    float s2  = vs[l];
    const float* yp = ys + (size_t)v * NT * NL + l;
    const float* rp = rs + (size_t)v * NT * NL + l;
    const float* dp = dtn + (size_t)v * NT1;

    // identity element
    float A00=1.f, A01=0.f, A10=0.f, A11=1.f;
    float b0=0.f, b1=0.f;
    float C00=0.f, C01=0.f, C11=0.f;
    float e0=0.f, e1=0.f;
    float J00=0.f, J01=0.f, J11=0.f;

    int tlo = (k == 0) ? 1 : CHF * k;
    int thi = CHF * k + CHF;
    for (int t = tlo; t < thi; ++t) {
        float dt = dp[t - 1];
        float y  = yp[(size_t)t * NL];
        float r  = rp[(size_t)t * NL];
        float a11,a12,a21,a22,q00,q01,q11;
        make_AQ(dt, lam, s2, a11,a12,a21,a22, q00,q01,q11);
        // leaf element
        float S  = q00 + r;
        float iS = __fdividef(1.0f, S);
        float k0 = q00 * iS;
        float k1 = q01 * iS;
        float om = 1.0f - k0;
        float lA00 = om * a11, lA01 = om * a12;
        float lA10 = a21 - k1 * a11, lA11 = a22 - k1 * a12;
        float lb0 = k0 * y, lb1 = k1 * y;
        float lC00 = om * q00, lC01 = om * q01, lC11 = q11 - k1 * q01;
        float ySi = y * iS;
        float le0 = a11 * ySi, le1 = a12 * ySi;
        float lJ00 = a11 * a11 * iS, lJ01 = a11 * a12 * iS, lJ11 = a12 * a12 * iS;

        // compose: E <- E (earlier) (x) leaf (later)
        float G00 = fmaf(C00, lJ00, fmaf(C01, lJ01, 1.0f));
        float G01 = fmaf(C00, lJ01, C01 * lJ11);
        float G10 = fmaf(C01, lJ00, C11 * lJ01);
        float G11 = fmaf(C01, lJ01, fmaf(C11, lJ11, 1.0f));
        float det = fmaf(G00, G11, -(G01 * G10));
        float id  = __fdividef(1.0f, det);
        float M00 =  G11 * id, M01 = -G01 * id, M10 = -G10 * id, M11 = G00 * id;
        float AM00 = fmaf(lA00, M00, lA01 * M10);
        float AM01 = fmaf(lA00, M01, lA01 * M11);
        float AM10 = fmaf(lA10, M00, lA11 * M10);
        float AM11 = fmaf(lA10, M01, lA11 * M11);
        float nA00 = fmaf(AM00, A00, AM01 * A10);
        float nA01 = fmaf(AM00, A01, AM01 * A11);
        float nA10 = fmaf(AM10, A00, AM11 * A10);
        float nA11 = fmaf(AM10, A01, AM11 * A11);
        float tb0 = fmaf(C00, le0, fmaf(C01, le1, b0));
        float tb1 = fmaf(C01, le0, fmaf(C11, le1, b1));
        float nb0 = fmaf(AM00, tb0, fmaf(AM01, tb1, lb0));
        float nb1 = fmaf(AM10, tb0, fmaf(AM11, tb1, lb1));
        float U00 = fmaf(AM00, C00, AM01 * C01);
        float U01 = fmaf(AM00, C01, AM01 * C11);
        float U10 = fmaf(AM10, C00, AM11 * C01);
        float U11 = fmaf(AM10, C01, AM11 * C11);
        float nC00 = fmaf(U00, lA00, fmaf(U01, lA01, lC00));
        float nC01 = fmaf(U00, lA10, fmaf(U01, lA11, lC01));
        float nC11 = fmaf(U10, lA10, fmaf(U11, lA11, lC11));
        float w0 = le0 - fmaf(lJ00, b0, lJ01 * b1);
        float w1 = le1 - fmaf(lJ01, b0, lJ11 * b1);
        float nw0 = fmaf(M00, w0, M10 * w1);
        float nw1 = fmaf(M01, w0, M11 * w1);
        float ne0 = fmaf(A00, nw0, fmaf(A10, nw1, e0));
        float ne1 = fmaf(A01, nw0, fmaf(A11, nw1, e1));
        float V00 = fmaf(M00, lJ00, M10 * lJ01);
        float V01 = fmaf(M00, lJ01, M10 * lJ11);
        float V10 = fmaf(M01, lJ00, M11 * lJ01);
        float V11 = fmaf(M01, lJ01, M11 * lJ11);
        float X00 = fmaf(A00, V00, A10 * V10);
        float X01 = fmaf(A00, V01, A10 * V11);
        float X10 = fmaf(A01, V00, A11 * V10);
        float X11 = fmaf(A01, V01, A11 * V11);
        float nJ00 = fmaf(X00, A00, fmaf(X01, A10, J00));
        float nJ01 = fmaf(X00, A01, fmaf(X01, A11, J01));
        float nJ11 = fmaf(X10, A01, fmaf(X11, A11, J11));

        A00=nA00; A01=nA01; A10=nA10; A11=nA11;
        b0=nb0; b1=nb1; C00=nC00; C01=nC01; C11=nC11;
        e0=ne0; e1=ne1; J00=nJ00; J01=nJ01; J11=nJ11;
    }
    int ix = k * NC + c;
    g_feA[ix] = make_float4(A00, A01, A10, A11);
    g_feB[ix] = make_float4(b0, b1, e0, e1);
    g_feC[ix] = make_float4(C00, C01, C11, J00);
    g_feJ[ix] = make_float2(J01, J11);
}

// ================= F3: serial scan over filter chunks =================
__global__ void __launch_bounds__(512) fscan_carry(
    const float* __restrict__ ys,
    const float* __restrict__ rs,
    const float* __restrict__ ls,
    const float* __restrict__ vs)
{
    int c = threadIdx.x;
    int v = c >> 4, l = c & 15;
    float lam = SQRT3 / ls[l];
    float s2  = vs[l];
    // e0 state: filtered at t=0 (matches F4's chunk-0 init exactly)
    float y0 = ys[(size_t)v * NT * NL + l];
    float r0 = rs[(size_t)v * NT * NL + l];
    float s  = s2 + r0;
    float inv = __fdividef(1.0f, s + F_JITTER);
    float w0 = s2 * inv;
    float m0 = w0 * y0, m1 = 0.0f;
    float p0 = s2 - w0 * s2, p1 = 0.0f, p2 = s2 * lam * lam;

    for (int k = 0; k < NKF; ++k) {
        int ix = k * NC + c;
        g_fbM[ix] = make_float2(m0, m1);
        g_fbP[ix] = make_float4(p0, p1, p2, 0.0f);
        float4 fA = g_feA[ix];
        float4 fB = g_feB[ix];
        float4 fC = g_feC[ix];
        float2 fJ = g_feJ[ix];
        float J00 = fC.w, J01 = fJ.x, J11 = fJ.y;
        // M = inv(I + P J)
        float G00 = fmaf(p0, J00, fmaf(p1, J01, 1.0f));
        float G01 = fmaf(p0, J01, p1 * J11);
        float G10 = fmaf(p1, J00, p2 * J01);
        float G11 = fmaf(p1, J01, fmaf(p2, J11, 1.0f));
        float det = fmaf(G00, G11, -(G01 * G10));
        float id  = __fdividef(1.0f, det);
        float M00 =  G11 * id, M01 = -G01 * id, M10 = -G10 * id, M11 = G00 * id;
        float tb0 = fmaf(p0, fB.z, fmaf(p1, fB.w, m0));
        float tb1 = fmaf(p1, fB.z, fmaf(p2, fB.w, m1));
        float mt0 = fmaf(M00, tb0, M01 * tb1);
        float mt1 = fmaf(M10, tb0, M11 * tb1);
        float nm0 = fmaf(fA.x, mt0, fmaf(fA.y, mt1, fB.x));
        float nm1 = fmaf(fA.z, mt0, fmaf(fA.w, mt1, fB.y));
        float V00 = fmaf(M00, p0, M01 * p1);
        float V01 = fmaf(M00, p1, M01 * p2);
        float V10 = fmaf(M10, p0, M11 * p1);
        float V11 = fmaf(M10, p1, M11 * p2);
        float X00 = fmaf(fA.x, V00, fA.y * V10);
        float X01 = fmaf(fA.x, V01, fA.y * V11);
        float X10 = fmaf(fA.z, V00, fA.w * V10);
        float X11 = fmaf(fA.z, V01, fA.w * V11);
        float np0 = fmaf(X00, fA.x, fmaf(X01, fA.y, fC.x));
        float np1 = fmaf(X00, fA.z, fmaf(X01, fA.w, fC.y));
        float np2 = fmaf(X10, fA.z, fmaf(X11, fA.w, fC.z));
        m0 = nm0; m1 = nm1; p0 = np0; p1 = np1; p2 = np2;
    }
}

// ================= F4: exact re-filter within chunks =================
__global__ void __launch_bounds__(512) frefilt(
    const float* __restrict__ dtn,
    const float* __restrict__ ys,
    const float* __restrict__ rs,
    const float* __restrict__ ls,
    const float* __restrict__ vs)
{
    int c = threadIdx.x;
    int k = blockIdx.x;
    int v = c >> 4, l = c & 15;
    const float* yp = ys + (size_t)v * NT * NL + l;
    const float* rp = rs + (size_t)v * NT * NL + l;
    const float* dp = dtn + (size_t)v * NT1;

    float m0, m1, p0, p1, p2;
    float acc = 0.0f;
    int tlo;
    if (k == 0) {
        float lam = SQRT3 / ls[l];
        float s2  = vs[l];
        float y = yp[0], r = rp[0];
        float s = s2 + r;
        float inv = __fdividef(1.0f, s + F_JITTER);
        float w0 = s2 * inv;
        m0 = w0 * y; m1 = 0.0f;
        p0 = s2 - w0 * s2; p1 = 0.0f; p2 = s2 * lam * lam;
        acc = fmaf(y * y, inv, __logf(s));
        g_mscr[c] = make_float2(m0, m1);
        g_pscr[c] = make_float4(p0, p1, p1, p2);
        tlo = 1;
    } else {
        float2 bm = g_fbM[k * NC + c];
        float4 bp = g_fbP[k * NC + c];
        m0 = bm.x; m1 = bm.y; p0 = bp.x; p1 = bp.y; p2 = bp.z;
        tlo = CHF * k;
    }
    int thi = CHF * k + CHF;
    for (int t = tlo; t < thi; ++t) {
        float dt = dp[t - 1];
        float y  = yp[(size_t)t * NL];
        float r  = rp[(size_t)t * NL];
        float a11,a12,a21,a22,q00,q01,q11;
        make_AQ(dt, SQRT3 / ls[l], vs[l], a11,a12,a21,a22, q00,q01,q11);
        acc += fstep(m0, m1, p0, p1, p2, a11,a12,a21,a22, q00,q01,q11, y, r);
        size_t ix = (size_t)t * NC + c;
        g_mscr[ix] = make_float2(m0, m1);
        g_pscr[ix] = make_float4(p0, p1, p1, p2);
    }
    g_lpp[k * NC + c] = acc;
}

// ================= S2: smoother chunk composites =================
__global__ void __launch_bounds__(512) sscan_chunk(
    const float* __restrict__ dtn,
    const float* __restrict__ ls,
    const float* __restrict__ vs)
{
    int c = threadIdx.x;
    int k = blockIdx.x;
    int v = c >> 4, l = c & 15;
    float lam = SQRT3 / ls[l];
    float s2  = vs[l];
    const float* dp = dtn + (size_t)v * NT1;

    float M00=1.f, M01=0.f, M10=0.f, M11=1.f, v0=0.f, v1=0.f;
    float L00=1.f, L01=0.f, L02=0.f;
    float L10=0.f, L11=1.f, L12=0.f;
    float L20=0.f, L21=0.f, L22=1.f;
    float wp0=0.f, wp1=0.f, wp2=0.f;

    int thi = (k == NKS - 1) ? 8190 : CHS * k + CHS - 1;
    int tlo = CHS * k;
    for (int t = thi; t >= tlo; --t) {
        float dt = dp[t];
        float a11,a12,a21,a22,q00,q01,q11;
        make_AQ(dt, lam, s2, a11,a12,a21,a22, q00,q01,q11);
        size_t ix = (size_t)t * NC + c;
        float2 mf = g_mscr[ix];
        float4 pf = g_pscr[ix];
        float g00,g01,g10,g11,h0,h1,W00,W01,W11;
        sgain(mf.x, mf.y, pf.x, pf.y, pf.w, a11,a12,a21,a22, q00,q01,q11,
              g00,g01,g10,g11, h0,h1, W00,W01,W11);
        // compose: new = elem_t o comp
        float nM00 = fmaf(g00, M00, g01 * M10);
        float nM01 = fmaf(g00, M01, g01 * M11);
        float nM10 = fmaf(g10, M00, g11 * M10);
        float nM11 = fmaf(g10, M01, g11 * M11);
        float nv0 = fmaf(g00, v0, fmaf(g01, v1, h0));
        float nv1 = fmaf(g10, v0, fmaf(g11, v1, h1));
        // T matrix
        float T00 = g00 * g00, T01 = 2.0f * g00 * g01, T02 = g01 * g01;
        float T10 = g00 * g10, T11 = fmaf(g00, g11, g01 * g10), T12 = g01 * g11;
        float T20 = g10 * g10, T21 = 2.0f * g10 * g11, T22 = g11 * g11;
        // L <- -(T L) ; w <- Wvec - T w
        float a0 = -fmaf(T00, L00, fmaf(T01, L10, T02 * L20));
        float a1 = -fmaf(T00, L01, fmaf(T01, L11, T02 * L21));
        float a2 = -fmaf(T00, L02, fmaf(T01, L12, T02 * L22));
        float b0_ = -fmaf(T10, L00, fmaf(T11, L10, T12 * L20));
        float b1_ = -fmaf(T10, L01, fmaf(T11, L11, T12 * L21));
        float b2_ = -fmaf(T10, L02, fmaf(T11, L12, T12 * L22));
        float c0 = -fmaf(T20, L00, fmaf(T21, L10, T22 * L20));
        float c1 = -fmaf(T20, L01, fmaf(T21, L11, T22 * L21));
        float c2 = -fmaf(T20, L02, fmaf(T21, L12, T22 * L22));
        float nw0 = W00 - fmaf(T00, wp0, fmaf(T01, wp1, T02 * wp2));
        float nw1 = W01 - fmaf(T10, wp0, fmaf(T11, wp1, T12 * wp2));
        float nw2 = W11 - fmaf(T20, wp0, fmaf(T21, wp1, T22 * wp2));
        M00=nM00; M01=nM01; M10=nM10; M11=nM11; v0=nv0; v1=nv1;
        L00=a0; L01=a1; L02=a2; L10=b0_; L11=b1_; L12=b2_; L20=c0; L21=c1; L22=c2;
        wp0=nw0; wp1=nw1; wp2=nw2;
    }
    int ix = k * NC + c;
    g_seM[ix]  = make_float4(M00, M01, M10, M11);
    g_seV[ix]  = make_float4(v0, v1, wp0, wp1);
    g_seL1[ix] = make_float4(L00, L01, L02, L10);
    g_seL2[ix] = make_float4(L11, L12, L20, L21);
    g_seL3[ix] = make_float2(L22, wp2);
}

// ================= S3: serial scan over smoother chunks (backward) =================
__global__ void __launch_bounds__(512) sscan_carry()
{
    int c = threadIdx.x;
    float2 mf = g_mscr[(size_t)(NT - 1) * NC + c];
    float4 pf = g_pscr[(size_t)(NT - 1) * NC + c];
    float m0 = mf.x, m1 = mf.y;
    float p0 = pf.x, p1 = pf.y, p2 = pf.w;
    for (int k = NKS - 1; k >= 0; --k) {
        int ix = k * NC + c;
        g_sbM[ix] = make_float2(m0, m1);
        g_sbP[ix] = make_float4(p0, p1, p2, 0.0f);
        float4 sM = g_seM[ix];
        float4 sV = g_seV[ix];
        float4 s1 = g_seL1[ix];
        float4 s2 = g_seL2[ix];
        float2 s3 = g_seL3[ix];
        float nm0 = fmaf(sM.x, m0, fmaf(sM.y, m1, sV.x));
        float nm1 = fmaf(sM.z, m0, fmaf(sM.w, m1, sV.y));
        float np0 = fmaf(s1.x, p0, fmaf(s1.y, p1, fmaf(s1.z, p2, sV.z)));
        float np1 = fmaf(s1.w, p0, fmaf(s2.x, p1, fmaf(s2.y, p2, sV.w)));
        float np2 = fmaf(s2.z, p0, fmaf(s2.w, p1, fmaf(s3.x, p2, s3.y)));
        m0 = nm0; m1 = nm1; p0 = np0; p1 = np1; p2 = np2;
    }
}

// ================= S4: exact re-smooth within chunks =================
__global__ void __launch_bounds__(512) sresmooth(
    const float* __restrict__ dtn,
    const float* __restrict__ ls,
    const float* __restrict__ vs)
{
    int c = threadIdx.x;
    int k = blockIdx.x;
    int v = c >> 4, l = c & 15;
    float lam = SQRT3 / ls[l];
    float s2  = vs[l];
    const float* dp = dtn + (size_t)v * NT1;

    float2 bm = g_sbM[k * NC + c];
    float4 bp = g_sbP[k * NC + c];
    float m0 = bm.x, m1 = bm.y;
    float p0 = bp.x, p1 = bp.y, p2 = bp.z;

    int thi;
    if (k == NKS - 1) {
        g_mzs[(size_t)(NT - 1) * NC + c] = m0;
        g_pzs[(size_t)(NT - 1) * NC + c] = p0;
        thi = 8190;
    } else {
        thi = CHS * k + CHS - 1;
    }
    int tlo = CHS * k;
    for (int t = thi; t >= tlo; --t) {
        float dt = dp[t];
        float a11,a12,a21,a22,q00,q01,q11;
        make_AQ(dt, lam, s2, a11,a12,a21,a22, q00,q01,q11);
        size_t ix = (size_t)t * NC + c;
        float2 mf = g_mscr[ix];
        float4 pf = g_pscr[ix];
        float g00,g01,g10,g11,h0,h1,W00,W01,W11;
        sgain(mf.x, mf.y, pf.x, pf.y, pf.w, a11,a12,a21,a22, q00,q01,q11,
              g00,g01,g10,g11, h0,h1, W00,W01,W11);
        float u00 = fmaf(g00, p0, g01 * p1);
        float u01 = fmaf(g00, p1, g01 * p2);
        float u10 = fmaf(g10, p0, g11 * p1);
        float u11 = fmaf(g10, p1, g11 * p2);
        float nm0 = fmaf(g00, m0, fmaf(g01, m1, h0));
        float nm1 = fmaf(g10, m0, fmaf(g11, m1, h1));
        p0 = W00 - fmaf(u00, g00, u01 * g01);
        p1 = W01 - fmaf(u00, g10, u01 * g11);
        p2 = W11 - fmaf(u10, g10, u11 * g11);
        m0 = nm0; m1 = nm1;
        g_mzs[ix] = m0;
        g_pzs[ix] = p0;
    }
}

// ---------------- tiled transposes: [t][c] scratch -> [c][t] output ----------------
template <typename ET>
__device__ __forceinline__ void transpose_body(const ET* __restrict__ src,
                                               ET* __restrict__ dst)
{
    __shared__ ET tile[32][33];
    int tx = threadIdx.x, ty = threadIdx.y;
    int t0 = blockIdx.x * 32;
    int c0 = blockIdx.y * 32;
    #pragma unroll
    for (int j = ty; j < 32; j += 8)
        tile[j][tx] = src[(size_t)(t0 + j) * NC + c0 + tx];
    __syncthreads();
    #pragma unroll
    for (int j = ty; j < 32; j += 8)
        dst[(size_t)(c0 + j) * NT + t0 + tx] = tile[tx][j];
}

__global__ void tr_m_kernel(float* out)  { transpose_body<float2>(g_mscr, (float2*)out); }
__global__ void tr_p_kernel(float* out)  { transpose_body<float4>(g_pscr, (float4*)(out + OFF_P)); }
__global__ void tr_mz_kernel(float* out) { transpose_body<float>(g_mzs, out + OFF_MZ); }
__global__ void tr_pz_kernel(float* out) { transpose_body<float>(g_pzs, out + OFF_PZ); }

// ---------------- deterministic log-lik reduction ----------------
__global__ void __launch_bounds__(512) logp_kernel(float* __restrict__ out)
{
    __shared__ double sh[NC];
    int c = threadIdx.x;
    double a = 0.0;
    for (int k = 0; k < NKF; ++k) a += (double)g_lpp[k * NC + c];
    sh[c] = -0.5 * (a + (double)NT * (double)F_LOG2PI);
    __syncthreads();
    if (c < NV) {
        double s = 0.0;
        #pragma unroll
        for (int l = 0; l < NL; ++l) s += sh[c * NL + l];
        out[OFF_LP + c] = (float)s;
    }
}

extern "C" void kernel_launch(void* const* d_in, const int* in_sizes, int n_in,
                              void* d_out, int out_size)
{
    const float* dtn = (const float*)d_in[0];
    const float* ys  = (const float*)d_in[1];
    const float* rs  = (const float*)d_in[2];
    const float* ls  = (const float*)d_in[3];
    const float* vs  = (const float*)d_in[4];
    float* out = (float*)d_out;

    dim3 trGrid(NT / 32, NC / 32);
    dim3 trBlk(32, 8);

    fscan_chunk<<<NKF, 512>>>(dtn, ys, rs, ls, vs);
    fscan_carry<<<1, 512>>>(ys, rs, ls, vs);
    frefilt<<<NKF, 512>>>(dtn, ys, rs, ls, vs);
    tr_m_kernel<<<trGrid, trBlk>>>(out);
    tr_p_kernel<<<trGrid, trBlk>>>(out);
    sscan_chunk<<<NKS, 512>>>(dtn, ls, vs);
    sscan_carry<<<1, 512>>>();
    sresmooth<<<NKS, 512>>>(dtn, ls, vs);
    tr_mz_kernel<<<trGrid, trBlk>>>(out);
    tr_pz_kernel<<<trGrid, trBlk>>>(out);
    logp_kernel<<<1, 512>>>(out);
}

// round 9
// speedup vs baseline: 14.5993x; 1.8323x over previous
#include <cuda_runtime.h>

#define NV 32
#define NT 8192
#define NT1 8191
#define NL 16
#define NC 512
#define NKF 256    /* filter chunks of 32 steps  */
#define CHF 32
#define NSF 16     /* filter supers of 16 chunks */
#define NKS 512    /* smoother chunks of 16 steps */
#define CHS 16
#define NSS 32     /* smoother supers of 16 chunks */

#define OFF_P  8388608u
#define OFF_MZ 25165824u
#define OFF_PZ 29360128u
#define OFF_LP 33554432u

#define F_JITTER 1e-6f
#define F_LOG2PI 1.8378770664093453f
#define SQRT3    1.7320508075688772f

// [t][c] scratch
__device__ float2 g_mscr[(size_t)NT * NC];
__device__ float4 g_pscr[(size_t)NT * NC];
__device__ float  g_mzs[(size_t)NT * NC];
__device__ float  g_pzs[(size_t)NT * NC];
__device__ float  g_lpp[NKF * NC];
// filter chunk composites (A, b, C, eta, J)
__device__ float4 g_feA[NKF * NC];
__device__ float4 g_feB[NKF * NC];
__device__ float4 g_feC[NKF * NC];
__device__ float2 g_feJ[NKF * NC];
// filter super composites
__device__ float4 g_sfA[NSF * NC];
__device__ float4 g_sfB[NSF * NC];
__device__ float4 g_sfC[NSF * NC];
__device__ float2 g_sfJ[NSF * NC];
// filter boundary states
__device__ float2 g_fbM[NKF * NC];
__device__ float4 g_fbP[NKF * NC];
__device__ float2 g_fbM2[NSF * NC];
__device__ float4 g_fbP2[NSF * NC];
// smoother chunk composites: m' = M m + v ; Pvec' = L Pvec + w
__device__ float4 g_seM[NKS * NC];   // M00,M01,M10,M11
__device__ float4 g_seV[NKS * NC];   // v0,v1,w0,w1
__device__ float4 g_seL1[NKS * NC];  // L00,L01,L02,L10
__device__ float4 g_seL2[NKS * NC];  // L11,L12,L20,L21
__device__ float2 g_seL3[NKS * NC];  // L22, w2
// smoother super composites
__device__ float4 g_ssM[NSS * NC];
__device__ float4 g_ssV[NSS * NC];
__device__ float4 g_ssL1[NSS * NC];
__device__ float4 g_ssL2[NSS * NC];
__device__ float2 g_ssL3[NSS * NC];
// smoother boundaries
__device__ float2 g_sbM[NKS * NC];
__device__ float4 g_sbP[NKS * NC];
__device__ float2 g_sbM2[NSS * NC];
__device__ float4 g_sbP2[NSS * NC];

// ---------------- A(dt), Q(dt) ----------------
__device__ __forceinline__ void make_AQ(float dt, float lam, float s2,
    float &a11, float &a12, float &a21, float &a22,
    float &q00, float &q01, float &q11)
{
    float x  = lam * dt;
    float e  = expf(-x);
    a11 = e * (1.0f + x);
    a12 = e * dt;
    a21 = -e * lam * x;
    a22 = e * (1.0f - x);
    float w  = 2.0f * x;
    float e2 = e * e;
    float poly = 1.0f/6.0f + w*(-1.0f/8.0f + w*(1.0f/20.0f + w*(-1.0f/72.0f + w*(1.0f/336.0f))));
    q00 = s2 * w * w * w * poly;
    q01 = 2.0f * s2 * lam * x * x * e2;
    q11 = s2 * lam * lam * (1.0f - e2 * (1.0f - w + 0.5f*w*w));
}

// ---------------- exact filter step ----------------
__device__ __forceinline__ float fstep(float &m0, float &m1,
                                       float &p00, float &p01, float &p11,
                                       float a11, float a12, float a21, float a22,
                                       float q00, float q01, float q11,
                                       float y, float r)
{
    float mp0 = fmaf(a11, m0, a12 * m1);
    float mp1 = fmaf(a21, m0, a22 * m1);
    float t00 = fmaf(a11, p00, a12 * p01);
    float t01 = fmaf(a11, p01, a12 * p11);
    float t10 = fmaf(a21, p00, a22 * p01);
    float t11 = fmaf(a21, p01, a22 * p11);
    float Pp00 = fmaf(t00, a11, fmaf(t01, a12, q00));
    float Pp01 = fmaf(t00, a21, fmaf(t01, a22, q01));
    float Pp11 = fmaf(t10, a21, fmaf(t11, a22, q11));
    float s   = Pp00 + r;
    float d   = y - mp0;
    float inv = __fdividef(1.0f, s + F_JITTER);
    float w0  = Pp00 * inv;
    float w1  = Pp01 * inv;
    m0  = fmaf(w0, d, mp0);
    m1  = fmaf(w1, d, mp1);
    p00 = fmaf(-w0, Pp00, Pp00);
    p01 = fmaf(-w0, Pp01, Pp01);
    p11 = fmaf(-w1, Pp01, Pp11);
    return fmaf(d * d, inv, __logf(s));
}

// ---------------- smoother gain quantities ----------------
__device__ __forceinline__ void sgain(float mf0, float mf1,
                                      float pf00, float pf01, float pf11,
                                      float a11, float a12, float a21, float a22,
                                      float q00, float q01, float q11,
                                      float &g00, float &g01, float &g10, float &g11,
                                      float &h0, float &h1,
                                      float &W00, float &W01, float &W11)
{
    float mp0 = fmaf(a11, mf0, a12 * mf1);
    float mp1 = fmaf(a21, mf0, a22 * mf1);
    float t00 = fmaf(a11, pf00, a12 * pf01);
    float t01 = fmaf(a11, pf01, a12 * pf11);
    float t10 = fmaf(a21, pf00, a22 * pf01);
    float t11 = fmaf(a21, pf01, a22 * pf11);
    float Pp00 = fmaf(t00, a11, fmaf(t01, a12, q00));
    float Pp01 = fmaf(t00, a21, fmaf(t01, a22, q01));
    float Pp11 = fmaf(t10, a21, fmaf(t11, a22, q11));
    float M00 = Pp00 + F_JITTER;
    float M11 = Pp11 + F_JITTER;
    float det = fmaf(M00, M11, -(Pp01 * Pp01));
    float di  = __fdividef(1.0f, det);
    float i00 =  M11 * di;
    float i01 = -Pp01 * di;
    float i11 =  M00 * di;
    g00 = fmaf(t00, i00, t10 * i01);
    g01 = fmaf(t00, i01, t10 * i11);
    g10 = fmaf(t01, i00, t11 * i01);
    g11 = fmaf(t01, i01, t11 * i11);
    h0 = mf0 - fmaf(g00, mp0, g01 * mp1);
    h1 = mf1 - fmaf(g10, mp0, g11 * mp1);
    float u00 = fmaf(g00, Pp00, g01 * Pp01);
    float u01 = fmaf(g00, Pp01, g01 * Pp11);
    float u10 = fmaf(g10, Pp00, g11 * Pp01);
    float u11 = fmaf(g10, Pp01, g11 * Pp11);
    W00 = pf00 + fmaf(u00, g00, u01 * g01);
    W01 = pf01 + fmaf(u00, g10, u01 * g11);
    W11 = pf11 + fmaf(u10, g10, u11 * g11);
}

// ---------------- filter element compose: E(earlier) (x) L(later) -> E ----------------
__device__ __forceinline__ void fcompose(
    float &A00, float &A01, float &A10, float &A11,
    float &b0, float &b1, float &C00, float &C01, float &C11,
    float &e0, float &e1, float &J00, float &J01, float &J11,
    float lA00, float lA01, float lA10, float lA11,
    float lb0, float lb1, float lC00, float lC01, float lC11,
    float le0, float le1, float lJ00, float lJ01, float lJ11)
{
    float G00 = fmaf(C00, lJ00, fmaf(C01, lJ01, 1.0f));
    float G01 = fmaf(C00, lJ01, C01 * lJ11);
    float G10 = fmaf(C01, lJ00, C11 * lJ01);
    float G11 = fmaf(C01, lJ01, fmaf(C11, lJ11, 1.0f));
    float det = fmaf(G00, G11, -(G01 * G10));
    float id  = __fdividef(1.0f, det);
    float M00 =  G11 * id, M01 = -G01 * id, M10 = -G10 * id, M11 = G00 * id;
    float AM00 = fmaf(lA00, M00, lA01 * M10);
    float AM01 = fmaf(lA00, M01, lA01 * M11);
    float AM10 = fmaf(lA10, M00, lA11 * M10);
    float AM11 = fmaf(lA10, M01, lA11 * M11);
    float nA00 = fmaf(AM00, A00, AM01 * A10);
    float nA01 = fmaf(AM00, A01, AM01 * A11);
    float nA10 = fmaf(AM10, A00, AM11 * A10);
    float nA11 = fmaf(AM10, A01, AM11 * A11);
    float tb0 = fmaf(C00, le0, fmaf(C01, le1, b0));
    float tb1 = fmaf(C01, le0, fmaf(C11, le1, b1));
    float nb0 = fmaf(AM00, tb0, fmaf(AM01, tb1, lb0));
    float nb1 = fmaf(AM10, tb0, fmaf(AM11, tb1, lb1));
    float U00 = fmaf(AM00, C00, AM01 * C01);
    float U01 = fmaf(AM00, C01, AM01 * C11);
    float U10 = fmaf(AM10, C00, AM11 * C01);
    float U11 = fmaf(AM10, C01, AM11 * C11);
    float nC00 = fmaf(U00, lA00, fmaf(U01, lA01, lC00));
    float nC01 = fmaf(U00, lA10, fmaf(U01, lA11, lC01));
    float nC11 = fmaf(U10, lA10, fmaf(U11, lA11, lC11));
    float w0 = le0 - fmaf(lJ00, b0, lJ01 * b1);
    float w1 = le1 - fmaf(lJ01, b0, lJ11 * b1);
    float nw0 = fmaf(M00, w0, M10 * w1);
    float nw1 = fmaf(M01, w0, M11 * w1);
    float ne0 = fmaf(A00, nw0, fmaf(A10, nw1, e0));
    float ne1 = fmaf(A01, nw0, fmaf(A11, nw1, e1));
    float V00 = fmaf(M00, lJ00, M10 * lJ01);
    float V01 = fmaf(M00, lJ01, M10 * lJ11);
    float V10 = fmaf(M01, lJ00, M11 * lJ01);
    float V11 = fmaf(M01, lJ01, M11 * lJ11);
    float X00 = fmaf(A00, V00, A10 * V10);
    float X01 = fmaf(A00, V01, A10 * V11);
    float X10 = fmaf(A01, V00, A11 * V10);
    float X11 = fmaf(A01, V01, A11 * V11);
    float nJ00 = fmaf(X00, A00, fmaf(X01, A10, J00));
    float nJ01 = fmaf(X00, A01, fmaf(X01, A11, J01));
    float nJ11 = fmaf(X10, A01, fmaf(X11, A11, J11));
    A00=nA00; A01=nA01; A10=nA10; A11=nA11;
    b0=nb0; b1=nb1; C00=nC00; C01=nC01; C11=nC11;
    e0=ne0; e1=ne1; J00=nJ00; J01=nJ01; J11=nJ11;
}

// ---------------- filter element applied to a state ----------------
__device__ __forceinline__ void fapply(
    float &m0, float &m1, float &p0, float &p1, float &p2,
    float A00, float A01, float A10, float A11,
    float b0, float b1, float C00, float C01, float C11,
    float e0f, float e1f, float J00, float J01, float J11)
{
    float G00 = fmaf(p0, J00, fmaf(p1, J01, 1.0f));
    float G01 = fmaf(p0, J01, p1 * J11);
    float G10 = fmaf(p1, J00, p2 * J01);
    float G11 = fmaf(p1, J01, fmaf(p2, J11, 1.0f));
    float det = fmaf(G00, G11, -(G01 * G10));
    float id  = __fdividef(1.0f, det);
    float M00 =  G11 * id, M01 = -G01 * id, M10 = -G10 * id, M11 = G00 * id;
    float tb0 = fmaf(p0, e0f, fmaf(p1, e1f, m0));
    float tb1 = fmaf(p1, e0f, fmaf(p2, e1f, m1));
    float mt0 = fmaf(M00, tb0, M01 * tb1);
    float mt1 = fmaf(M10, tb0, M11 * tb1);
    float nm0 = fmaf(A00, mt0, fmaf(A01, mt1, b0));
    float nm1 = fmaf(A10, mt0, fmaf(A11, mt1, b1));
    float V00 = fmaf(M00, p0, M01 * p1);
    float V01 = fmaf(M00, p1, M01 * p2);
    float V10 = fmaf(M10, p0, M11 * p1);
    float V11 = fmaf(M10, p1, M11 * p2);
    float X00 = fmaf(A00, V00, A01 * V10);
    float X01 = fmaf(A00, V01, A01 * V11);
    float X10 = fmaf(A10, V00, A11 * V10);
    float X11 = fmaf(A10, V01, A11 * V11);
    float np0 = fmaf(X00, A00, fmaf(X01, A01, C00));
    float np1 = fmaf(X00, A10, fmaf(X01, A11, C01));
    float np2 = fmaf(X10, A10, fmaf(X11, A11, C11));
    m0 = nm0; m1 = nm1; p0 = np0; p1 = np1; p2 = np2;
}

// ---------------- smoother affine apply: state <- elem(state) ----------------
__device__ __forceinline__ void sapply(
    float &m0, float &m1, float &p0, float &p1, float &p2,
    float4 sM, float4 sV, float4 s1, float4 s2, float2 s3)
{
    float nm0 = fmaf(sM.x, m0, fmaf(sM.y, m1, sV.x));
    float nm1 = fmaf(sM.z, m0, fmaf(sM.w, m1, sV.y));
    float np0 = fmaf(s1.x, p0, fmaf(s1.y, p1, fmaf(s1.z, p2, sV.z)));
    float np1 = fmaf(s1.w, p0, fmaf(s2.x, p1, fmaf(s2.y, p2, sV.w)));
    float np2 = fmaf(s2.z, p0, fmaf(s2.w, p1, fmaf(s3.x, p2, s3.y)));
    m0 = nm0; m1 = nm1; p0 = np0; p1 = np1; p2 = np2;
}

// ================= F2: filter chunk composites =================
__global__ void __launch_bounds__(512) fscan_chunk(
    const float* __restrict__ dtn,
    const float* __restrict__ ys,
    const float* __restrict__ rs,
    const float* __restrict__ ls,
    const float* __restrict__ vs)
{
    int c = threadIdx.x;
    int k = blockIdx.x;
    int v = c >> 4, l = c & 15;
    float lam = SQRT3 / ls[l];
    float s2  = vs[l];
    const float* yp = ys + (size_t)v * NT * NL + l;
    const float* rp = rs + (size_t)v * NT * NL + l;
    const float* dp = dtn + (size_t)v * NT1;

    float A00=1.f, A01=0.f, A10=0.f, A11=1.f;
    float b0=0.f, b1=0.f;
    float C00=0.f, C01=0.f, C11=0.f;
    float e0=0.f, e1=0.f;
    float J00=0.f, J01=0.f, J11=0.f;

    int tlo = (k == 0) ? 1 : CHF * k;
    int thi = CHF * k + CHF;
    for (int t = tlo; t < thi; ++t) {
        float dt = dp[t - 1];
        float y  = yp[(size_t)t * NL];
        float r  = rp[(size_t)t * NL];
        float a11,a12,a21,a22,q00,q01,q11;
        make_AQ(dt, lam, s2, a11,a12,a21,a22, q00,q01,q11);
        float S  = q00 + r;
        float iS = __fdividef(1.0f, S);
        float k0 = q00 * iS;
        float k1 = q01 * iS;
        float om = 1.0f - k0;
        float lA00 = om * a11, lA01 = om * a12;
        float lA10 = a21 - k1 * a11, lA11 = a22 - k1 * a12;
        float lb0 = k0 * y, lb1 = k1 * y;
        float lC00 = om * q00, lC01 = om * q01, lC11 = q11 - k1 * q01;
        float ySi = y * iS;
        float le0 = a11 * ySi, le1 = a12 * ySi;
        float lJ00 = a11 * a11 * iS, lJ01 = a11 * a12 * iS, lJ11 = a12 * a12 * iS;
        fcompose(A00,A01,A10,A11,b0,b1,C00,C01,C11,e0,e1,J00,J01,J11,
                 lA00,lA01,lA10,lA11,lb0,lb1,lC00,lC01,lC11,le0,le1,lJ00,lJ01,lJ11);
    }
    int ix = k * NC + c;
    g_feA[ix] = make_float4(A00, A01, A10, A11);
    g_feB[ix] = make_float4(b0, b1, e0, e1);
    g_feC[ix] = make_float4(C00, C01, C11, J00);
    g_feJ[ix] = make_float2(J01, J11);
}

// ================= F2b: compose 16 chunks -> super composites =================
__global__ void __launch_bounds__(512) fcarry1()
{
    int c = threadIdx.x;
    int s = blockIdx.x;
    float A00=1.f, A01=0.f, A10=0.f, A11=1.f;
    float b0=0.f, b1=0.f, C00=0.f, C01=0.f, C11=0.f;
    float e0=0.f, e1=0.f, J00=0.f, J01=0.f, J11=0.f;
    #pragma unroll 4
    for (int j = 0; j < 16; ++j) {
        int ix = (s * 16 + j) * NC + c;
        float4 fA = g_feA[ix];
        float4 fB = g_feB[ix];
        float4 fC = g_feC[ix];
        float2 fJ = g_feJ[ix];
        fcompose(A00,A01,A10,A11,b0,b1,C00,C01,C11,e0,e1,J00,J01,J11,
                 fA.x,fA.y,fA.z,fA.w, fB.x,fB.y, fC.x,fC.y,fC.z,
                 fB.z,fB.w, fC.w,fJ.x,fJ.y);
    }
    int ox = s * NC + c;
    g_sfA[ox] = make_float4(A00, A01, A10, A11);
    g_sfB[ox] = make_float4(b0, b1, e0, e1);
    g_sfC[ox] = make_float4(C00, C01, C11, J00);
    g_sfJ[ox] = make_float2(J01, J11);
}

// ================= F3a: serial scan over 16 supers =================
__global__ void __launch_bounds__(512) fcarry2(
    const float* __restrict__ ys,
    const float* __restrict__ rs,
    const float* __restrict__ ls,
    const float* __restrict__ vs)
{
    int c = threadIdx.x;
    int v = c >> 4, l = c & 15;
    float lam = SQRT3 / ls[l];
    float s2  = vs[l];
    float y0 = ys[(size_t)v * NT * NL + l];
    float r0 = rs[(size_t)v * NT * NL + l];
    float s  = s2 + r0;
    float inv = __fdividef(1.0f, s + F_JITTER);
    float w0 = s2 * inv;
    float m0 = w0 * y0, m1 = 0.0f;
    float p0 = s2 - w0 * s2, p1 = 0.0f, p2 = s2 * lam * lam;

    #pragma unroll
    for (int ss = 0; ss < NSF; ++ss) {
        int ix = ss * NC + c;
        g_fbM2[ix] = make_float2(m0, m1);
        g_fbP2[ix] = make_float4(p0, p1, p2, 0.0f);
        float4 fA = g_sfA[ix];
        float4 fB = g_sfB[ix];
        float4 fC = g_sfC[ix];
        float2 fJ = g_sfJ[ix];
        fapply(m0,m1,p0,p1,p2,
               fA.x,fA.y,fA.z,fA.w, fB.x,fB.y, fC.x,fC.y,fC.z,
               fB.z,fB.w, fC.w,fJ.x,fJ.y);
    }
}

// ================= F3b: expand super boundaries -> chunk boundaries =================
__global__ void __launch_bounds__(512) fcarry3()
{
    int c = threadIdx.x;
    int s = blockIdx.x;
    float2 bm = g_fbM2[s * NC + c];
    float4 bp = g_fbP2[s * NC + c];
    float m0 = bm.x, m1 = bm.y, p0 = bp.x, p1 = bp.y, p2 = bp.z;
    #pragma unroll 4
    for (int j = 0; j < 16; ++j) {
        int k = s * 16 + j;
        int ix = k * NC + c;
        g_fbM[ix] = make_float2(m0, m1);
        g_fbP[ix] = make_float4(p0, p1, p2, 0.0f);
        float4 fA = g_feA[ix];
        float4 fB = g_feB[ix];
        float4 fC = g_feC[ix];
        float2 fJ = g_feJ[ix];
        fapply(m0,m1,p0,p1,p2,
               fA.x,fA.y,fA.z,fA.w, fB.x,fB.y, fC.x,fC.y,fC.z,
               fB.z,fB.w, fC.w,fJ.x,fJ.y);
    }
}

// ================= F4: exact re-filter within chunks =================
__global__ void __launch_bounds__(512) frefilt(
    const float* __restrict__ dtn,
    const float* __restrict__ ys,
    const float* __restrict__ rs,
    const float* __restrict__ ls,
    const float* __restrict__ vs)
{
    int c = threadIdx.x;
    int k = blockIdx.x;
    int v = c >> 4, l = c & 15;
    const float* yp = ys + (size_t)v * NT * NL + l;
    const float* rp = rs + (size_t)v * NT * NL + l;
    const float* dp = dtn + (size_t)v * NT1;

    float m0, m1, p0, p1, p2;
    float acc = 0.0f;
    int tlo;
    if (k == 0) {
        float lam = SQRT3 / ls[l];
        float s2  = vs[l];
        float y = yp[0], r = rp[0];
        float s = s2 + r;
        float inv = __fdividef(1.0f, s + F_JITTER);
        float w0 = s2 * inv;
        m0 = w0 * y; m1 = 0.0f;
        p0 = s2 - w0 * s2; p1 = 0.0f; p2 = s2 * lam * lam;
        acc = fmaf(y * y, inv, __logf(s));
        g_mscr[c] = make_float2(m0, m1);
        g_pscr[c] = make_float4(p0, p1, p1, p2);
        tlo = 1;
    } else {
        float2 bm = g_fbM[k * NC + c];
        float4 bp = g_fbP[k * NC + c];
        m0 = bm.x; m1 = bm.y; p0 = bp.x; p1 = bp.y; p2 = bp.z;
        tlo = CHF * k;
    }
    int thi = CHF * k + CHF;
    for (int t = tlo; t < thi; ++t) {
        float dt = dp[t - 1];
        float y  = yp[(size_t)t * NL];
        float r  = rp[(size_t)t * NL];
        float a11,a12,a21,a22,q00,q01,q11;
        make_AQ(dt, SQRT3 / ls[l], vs[l], a11,a12,a21,a22, q00,q01,q11);
        acc += fstep(m0, m1, p0, p1, p2, a11,a12,a21,a22, q00,q01,q11, y, r);
        size_t ix = (size_t)t * NC + c;
        g_mscr[ix] = make_float2(m0, m1);
        g_pscr[ix] = make_float4(p0, p1, p1, p2);
    }
    g_lpp[k * NC + c] = acc;
}

// ================= S2: smoother chunk composites =================
__global__ void __launch_bounds__(512) sscan_chunk(
    const float* __restrict__ dtn,
    const float* __restrict__ ls,
    const float* __restrict__ vs)
{
    int c = threadIdx.x;
    int k = blockIdx.x;
    int v = c >> 4, l = c & 15;
    float lam = SQRT3 / ls[l];
    float s2  = vs[l];
    const float* dp = dtn + (size_t)v * NT1;

    float M00=1.f, M01=0.f, M10=0.f, M11=1.f, v0=0.f, v1=0.f;
    float L00=1.f, L01=0.f, L02=0.f;
    float L10=0.f, L11=1.f, L12=0.f;
    float L20=0.f, L21=0.f, L22=1.f;
    float wp0=0.f, wp1=0.f, wp2=0.f;

    int thi = (k == NKS - 1) ? 8190 : CHS * k + CHS - 1;
    int tlo = CHS * k;
    for (int t = thi; t >= tlo; --t) {
        float dt = dp[t];
        float a11,a12,a21,a22,q00,q01,q11;
        make_AQ(dt, lam, s2, a11,a12,a21,a22, q00,q01,q11);
        size_t ix = (size_t)t * NC + c;
        float2 mf = g_mscr[ix];
        float4 pf = g_pscr[ix];
        float g00,g01,g10,g11,h0,h1,W00,W01,W11;
        sgain(mf.x, mf.y, pf.x, pf.y, pf.w, a11,a12,a21,a22, q00,q01,q11,
              g00,g01,g10,g11, h0,h1, W00,W01,W11);
        float nM00 = fmaf(g00, M00, g01 * M10);
        float nM01 = fmaf(g00, M01, g01 * M11);
        float nM10 = fmaf(g10, M00, g11 * M10);
        float nM11 = fmaf(g10, M01, g11 * M11);
        float nv0 = fmaf(g00, v0, fmaf(g01, v1, h0));
        float nv1 = fmaf(g10, v0, fmaf(g11, v1, h1));
        float T00 = g00 * g00, T01 = 2.0f * g00 * g01, T02 = g01 * g01;
        float T10 = g00 * g10, T11 = fmaf(g00, g11, g01 * g10), T12 = g01 * g11;
        float T20 = g10 * g10, T21 = 2.0f * g10 * g11, T22 = g11 * g11;
        float a0 = -fmaf(T00, L00, fmaf(T01, L10, T02 * L20));
        float a1 = -fmaf(T00, L01, fmaf(T01, L11, T02 * L21));
        float a2 = -fmaf(T00, L02, fmaf(T01, L12, T02 * L22));
        float b0_ = -fmaf(T10, L00, fmaf(T11, L10, T12 * L20));
        float b1_ = -fmaf(T10, L01, fmaf(T11, L11, T12 * L21));
        float b2_ = -fmaf(T10, L02, fmaf(T11, L12, T12 * L22));
        float c0 = -fmaf(T20, L00, fmaf(T21, L10, T22 * L20));
        float c1 = -fmaf(T20, L01, fmaf(T21, L11, T22 * L21));
        float c2 = -fmaf(T20, L02, fmaf(T21, L12, T22 * L22));
        float nw0 = W00 - fmaf(T00, wp0, fmaf(T01, wp1, T02 * wp2));
        float nw1 = W01 - fmaf(T10, wp0, fmaf(T11, wp1, T12 * wp2));
        float nw2 = W11 - fmaf(T20, wp0, fmaf(T21, wp1, T22 * wp2));
        M00=nM00; M01=nM01; M10=nM10; M11=nM11; v0=nv0; v1=nv1;
        L00=a0; L01=a1; L02=a2; L10=b0_; L11=b1_; L12=b2_; L20=c0; L21=c1; L22=c2;
        wp0=nw0; wp1=nw1; wp2=nw2;
    }
    int ix = k * NC + c;
    g_seM[ix]  = make_float4(M00, M01, M10, M11);
    g_seV[ix]  = make_float4(v0, v1, wp0, wp1);
    g_seL1[ix] = make_float4(L00, L01, L02, L10);
    g_seL2[ix] = make_float4(L11, L12, L20, L21);
    g_seL3[ix] = make_float2(L22, wp2);
}

// ================= S2b: compose 16 smoother chunks -> super =================
__global__ void __launch_bounds__(512) scarry1()
{
    int c = threadIdx.x;
    int s = blockIdx.x;
    // accumulated = comp (maps end-state -> start-state of covered range)
    float M00=1.f, M01=0.f, M10=0.f, M11=1.f, v0=0.f, v1=0.f;
    float L00=1.f, L01=0.f, L02=0.f;
    float L10=0.f, L11=1.f, L12=0.f;
    float L20=0.f, L21=0.f, L22=1.f;
    float w0=0.f, w1=0.f, w2=0.f;
    // iterate chunk k from high to low: comp <- elem_k o comp
    #pragma unroll 4
    for (int j = 15; j >= 0; --j) {
        int ix = (s * 16 + j) * NC + c;
        float4 eM = g_seM[ix];
        float4 eV = g_seV[ix];
        float4 e1 = g_seL1[ix];
        float4 e2 = g_seL2[ix];
        float2 e3 = g_seL3[ix];
        // mean: M <- eM * M ; v <- eM * v + ev
        float nM00 = fmaf(eM.x, M00, eM.y * M10);
        float nM01 = fmaf(eM.x, M01, eM.y * M11);
        float nM10 = fmaf(eM.z, M00, eM.w * M10);
        float nM11 = fmaf(eM.z, M01, eM.w * M11);
        float nv0 = fmaf(eM.x, v0, fmaf(eM.y, v1, eV.x));
        float nv1 = fmaf(eM.z, v0, fmaf(eM.w, v1, eV.y));
        // cov: L <- eL * L ; w <- eL * w + ew
        float E00=e1.x, E01=e1.y, E02=e1.z, E10=e1.w, E11=e2.x, E12=e2.y;
        float E20=e2.z, E21=e2.w, E22=e3.x;
        float a0 = fmaf(E00, L00, fmaf(E01, L10, E02 * L20));
        float a1 = fmaf(E00, L01, fmaf(E01, L11, E02 * L21));
        float a2 = fmaf(E00, L02, fmaf(E01, L12, E02 * L22));
        float bb0 = fmaf(E10, L00, fmaf(E11, L10, E12 * L20));
        float bb1 = fmaf(E10, L01, fmaf(E11, L11, E12 * L21));
        float bb2 = fmaf(E10, L02, fmaf(E11, L12, E12 * L22));
        float cc0 = fmaf(E20, L00, fmaf(E21, L10, E22 * L20));
        float cc1 = fmaf(E20, L01, fmaf(E21, L11, E22 * L21));
        float cc2 = fmaf(E20, L02, fmaf(E21, L12, E22 * L22));
        float nw0 = fmaf(E00, w0, fmaf(E01, w1, fmaf(E02, w2, eV.z)));
        float nw1 = fmaf(E10, w0, fmaf(E11, w1, fmaf(E12, w2, eV.w)));
        float nw2 = fmaf(E20, w0, fmaf(E21, w1, fmaf(E22, w2, e3.y)));
        M00=nM00; M01=nM01; M10=nM10; M11=nM11; v0=nv0; v1=nv1;
        L00=a0; L01=a1; L02=a2; L10=bb0; L11=bb1; L12=bb2; L20=cc0; L21=cc1; L22=cc2;
        w0=nw0; w1=nw1; w2=nw2;
    }
    int ox = s * NC + c;
    g_ssM[ox]  = make_float4(M00, M01, M10, M11);
    g_ssV[ox]  = make_float4(v0, v1, w0, w1);
    g_ssL1[ox] = make_float4(L00, L01, L02, L10);
    g_ssL2[ox] = make_float4(L11, L12, L20, L21);
    g_ssL3[ox] = make_float2(L22, w2);
}

// ================= S3a: serial scan over 32 supers (backward) =================
__global__ void __launch_bounds__(512) scarry2()
{
    int c = threadIdx.x;
    float2 mf = g_mscr[(size_t)(NT - 1) * NC + c];
    float4 pf = g_pscr[(size_t)(NT - 1) * NC + c];
    float m0 = mf.x, m1 = mf.y;
    float p0 = pf.x, p1 = pf.y, p2 = pf.w;
    #pragma unroll
    for (int s = NSS - 1; s >= 0; --s) {
        int ix = s * NC + c;
        g_sbM2[ix] = make_float2(m0, m1);
        g_sbP2[ix] = make_float4(p0, p1, p2, 0.0f);
        sapply(m0, m1, p0, p1, p2,
               g_ssM[ix], g_ssV[ix], g_ssL1[ix], g_ssL2[ix], g_ssL3[ix]);
    }
}

// ================= S3b: expand super -> chunk boundaries =================
__global__ void __launch_bounds__(512) scarry3()
{
    int c = threadIdx.x;
    int s = blockIdx.x;
    float2 bm = g_sbM2[s * NC + c];
    float4 bp = g_sbP2[s * NC + c];
    float m0 = bm.x, m1 = bm.y, p0 = bp.x, p1 = bp.y, p2 = bp.z;
    #pragma unroll 4
    for (int j = 15; j >= 0; --j) {
        int k = s * 16 + j;
        int ix = k * NC + c;
        g_sbM[ix] = make_float2(m0, m1);
        g_sbP[ix] = make_float4(p0, p1, p2, 0.0f);
        sapply(m0, m1, p0, p1, p2,
               g_seM[ix], g_seV[ix], g_seL1[ix], g_seL2[ix], g_seL3[ix]);
    }
}

// ================= S4: exact re-smooth within chunks =================
__global__ void __launch_bounds__(512) sresmooth(
    const float* __restrict__ dtn,
    const float* __restrict__ ls,
    const float* __restrict__ vs)
{
    int c = threadIdx.x;
    int k = blockIdx.x;
    int v = c >> 4, l = c & 15;
    float lam = SQRT3 / ls[l];
    float s2  = vs[l];
    const float* dp = dtn + (size_t)v * NT1;

    float2 bm = g_sbM[k * NC + c];
    float4 bp = g_sbP[k * NC + c];
    float m0 = bm.x, m1 = bm.y;
    float p0 = bp.x, p1 = bp.y, p2 = bp.z;

    int thi;
    if (k == NKS - 1) {
        g_mzs[(size_t)(NT - 1) * NC + c] = m0;
        g_pzs[(size_t)(NT - 1) * NC + c] = p0;
        thi = 8190;
    } else {
        thi = CHS * k + CHS - 1;
    }
    int tlo = CHS * k;
    for (int t = thi; t >= tlo; --t) {
        float dt = dp[t];
        float a11,a12,a21,a22,q00,q01,q11;
        make_AQ(dt, lam, s2, a11,a12,a21,a22, q00,q01,q11);
        size_t ix = (size_t)t * NC + c;
        float2 mf = g_mscr[ix];
        float4 pf = g_pscr[ix];
        float g00,g01,g10,g11,h0,h1,W00,W01,W11;
        sgain(mf.x, mf.y, pf.x, pf.y, pf.w, a11,a12,a21,a22, q00,q01,q11,
              g00,g01,g10,g11, h0,h1, W00,W01,W11);
        float u00 = fmaf(g00, p0, g01 * p1);
        float u01 = fmaf(g00, p1, g01 * p2);
        float u10 = fmaf(g10, p0, g11 * p1);
        float u11 = fmaf(g10, p1, g11 * p2);
        float nm0 = fmaf(g00, m0, fmaf(g01, m1, h0));
        float nm1 = fmaf(g10, m0, fmaf(g11, m1, h1));
        p0 = W00 - fmaf(u00, g00, u01 * g01);
        p1 = W01 - fmaf(u00, g10, u01 * g11);
        p2 = W11 - fmaf(u10, g10, u11 * g11);
        m0 = nm0; m1 = nm1;
        g_mzs[ix] = m0;
        g_pzs[ix] = p0;
    }
}

// ---------------- tiled transposes: [t][c] scratch -> [c][t] output ----------------
template <typename ET>
__device__ __forceinline__ void transpose_body(const ET* __restrict__ src,
                                               ET* __restrict__ dst)
{
    __shared__ ET tile[32][33];
    int tx = threadIdx.x, ty = threadIdx.y;
    int t0 = blockIdx.x * 32;
    int c0 = blockIdx.y * 32;
    #pragma unroll
    for (int j = ty; j < 32; j += 8)
        tile[j][tx] = src[(size_t)(t0 + j) * NC + c0 + tx];
    __syncthreads();
    #pragma unroll
    for (int j = ty; j < 32; j += 8)
        dst[(size_t)(c0 + j) * NT + t0 + tx] = tile[tx][j];
}

__global__ void tr_m_kernel(float* out)  { transpose_body<float2>(g_mscr, (float2*)out); }
__global__ void tr_p_kernel(float* out)  { transpose_body<float4>(g_pscr, (float4*)(out + OFF_P)); }
__global__ void tr_mz_kernel(float* out) { transpose_body<float>(g_mzs, out + OFF_MZ); }
__global__ void tr_pz_kernel(float* out) { transpose_body<float>(g_pzs, out + OFF_PZ); }

// ---------------- deterministic log-lik reduction ----------------
__global__ void __launch_bounds__(512) logp_kernel(float* __restrict__ out)
{
    __shared__ double sh[NC];
    int c = threadIdx.x;
    double a = 0.0;
    for (int k = 0; k < NKF; ++k) a += (double)g_lpp[k * NC + c];
    sh[c] = -0.5 * (a + (double)NT * (double)F_LOG2PI);
    __syncthreads();
    if (c < NV) {
        double s = 0.0;
        #pragma unroll
        for (int l = 0; l < NL; ++l) s += sh[c * NL + l];
        out[OFF_LP + c] = (float)s;
    }
}

extern "C" void kernel_launch(void* const* d_in, const int* in_sizes, int n_in,
                              void* d_out, int out_size)
{
    const float* dtn = (const float*)d_in[0];
    const float* ys  = (const float*)d_in[1];
    const float* rs  = (const float*)d_in[2];
    const float* ls  = (const float*)d_in[3];
    const float* vs  = (const float*)d_in[4];
    float* out = (float*)d_out;

    dim3 trGrid(NT / 32, NC / 32);
    dim3 trBlk(32, 8);

    fscan_chunk<<<NKF, 512>>>(dtn, ys, rs, ls, vs);
    fcarry1<<<NSF, 512>>>();
    fcarry2<<<1, 512>>>(ys, rs, ls, vs);
    fcarry3<<<NSF, 512>>>();
    frefilt<<<NKF, 512>>>(dtn, ys, rs, ls, vs);
    tr_m_kernel<<<trGrid, trBlk>>>(out);
    tr_p_kernel<<<trGrid, trBlk>>>(out);
    sscan_chunk<<<NKS, 512>>>(dtn, ls, vs);
    scarry1<<<NSS, 512>>>();
    scarry2<<<1, 512>>>();
    scarry3<<<NSS, 512>>>();
    sresmooth<<<NKS, 512>>>(dtn, ls, vs);
    tr_mz_kernel<<<trGrid, trBlk>>>(out);
    tr_pz_kernel<<<trGrid, trBlk>>>(out);
    logp_kernel<<<1, 512>>>(out);
}

// round 12
// speedup vs baseline: 15.1004x; 1.0343x over previous
#include <cuda_runtime.h>

#define NV 32
#define NT 8192
#define NT1 8191
#define NL 16
#define NC 512
#define NKF 256    /* chunks of 32 steps */
#define CHF 32
#define NSF 16     /* supers of 16 chunks */

#define OFF_P  8388608u
#define OFF_MZ 25165824u
#define OFF_PZ 29360128u
#define OFF_LP 33554432u

#define F_JITTER 1e-6f
#define F_LOG2PI 1.8378770664093453f
#define SQRT3    1.7320508075688772f

#define SOLVE_SMEM 101376

__device__ float  g_lpp[NKF * NC];
// filter chunk composites (A, b, C, eta, J)
__device__ float4 g_feA[NKF * NC];
__device__ float4 g_feB[NKF * NC];
__device__ float4 g_feC[NKF * NC];
__device__ float2 g_feJ[NKF * NC];
// filter super composites
__device__ float4 g_sfA[NSF * NC];
__device__ float4 g_sfB[NSF * NC];
__device__ float4 g_sfC[NSF * NC];
__device__ float2 g_sfJ[NSF * NC];
// filter boundaries (state at chunk start - 1)
__device__ float2 g_fbM[NKF * NC];
__device__ float4 g_fbP[NKF * NC];
__device__ float2 g_fbM2[NSF * NC];
__device__ float4 g_fbP2[NSF * NC];
// filtered state at t = NT-1
__device__ float2 g_ffM[NC];
__device__ float4 g_ffP[NC];
// smoother chunk composites: m' = M m + v ; Pvec' = L Pvec + w
__device__ float4 g_seM[NKF * NC];
__device__ float4 g_seV[NKF * NC];   // v0,v1,w0,w1
__device__ float4 g_seL1[NKF * NC];  // L00,L01,L02,L10
__device__ float4 g_seL2[NKF * NC];  // L11,L12,L20,L21
__device__ float2 g_seL3[NKF * NC];  // L22, w2
// smoother super composites
__device__ float4 g_ssM[NSF * NC];
__device__ float4 g_ssV[NSF * NC];
__device__ float4 g_ssL1[NSF * NC];
__device__ float4 g_ssL2[NSF * NC];
__device__ float2 g_ssL3[NSF * NC];
// smoother boundaries (smoothed state at chunk end + 1)
__device__ float2 g_sbM[NKF * NC];
__device__ float4 g_sbP[NKF * NC];
__device__ float2 g_sbM2[NSF * NC];
__device__ float4 g_sbP2[NSF * NC];

// ---------------- A(dt), Q(dt) ----------------
__device__ __forceinline__ void make_AQ(float dt, float lam, float s2,
    float &a11, float &a12, float &a21, float &a22,
    float &q00, float &q01, float &q11)
{
    float x  = lam * dt;
    float e  = expf(-x);
    a11 = e * (1.0f + x);
    a12 = e * dt;
    a21 = -e * lam * x;
    a22 = e * (1.0f - x);
    float w  = 2.0f * x;
    float e2 = e * e;
    float poly = 1.0f/6.0f + w*(-1.0f/8.0f + w*(1.0f/20.0f + w*(-1.0f/72.0f + w*(1.0f/336.0f))));
    q00 = s2 * w * w * w * poly;
    q01 = 2.0f * s2 * lam * x * x * e2;
    q11 = s2 * lam * lam * (1.0f - e2 * (1.0f - w + 0.5f*w*w));
}

// ---------------- exact filter step ----------------
__device__ __forceinline__ float fstep(float &m0, float &m1,
                                       float &p00, float &p01, float &p11,
                                       float a11, float a12, float a21, float a22,
                                       float q00, float q01, float q11,
                                       float y, float r)
{
    float mp0 = fmaf(a11, m0, a12 * m1);
    float mp1 = fmaf(a21, m0, a22 * m1);
    float t00 = fmaf(a11, p00, a12 * p01);
    float t01 = fmaf(a11, p01, a12 * p11);
    float t10 = fmaf(a21, p00, a22 * p01);
    float t11 = fmaf(a21, p01, a22 * p11);
    float Pp00 = fmaf(t00, a11, fmaf(t01, a12, q00));
    float Pp01 = fmaf(t00, a21, fmaf(t01, a22, q01));
    float Pp11 = fmaf(t10, a21, fmaf(t11, a22, q11));
    float s   = Pp00 + r;
    float d   = y - mp0;
    float inv = __fdividef(1.0f, s + F_JITTER);
    float w0  = Pp00 * inv;
    float w1  = Pp01 * inv;
    m0  = fmaf(w0, d, mp0);
    m1  = fmaf(w1, d, mp1);
    p00 = fmaf(-w0, Pp00, Pp00);
    p01 = fmaf(-w0, Pp01, Pp01);
    p11 = fmaf(-w1, Pp01, Pp11);
    return fmaf(d * d, inv, __logf(s));
}

// ---------------- smoother gain quantities ----------------
__device__ __forceinline__ void sgain(float mf0, float mf1,
                                      float pf00, float pf01, float pf11,
                                      float a11, float a12, float a21, float a22,
                                      float q00, float q01, float q11,
                                      float &g00, float &g01, float &g10, float &g11,
                                      float &h0, float &h1,
                                      float &W00, float &W01, float &W11)
{
    float mp0 = fmaf(a11, mf0, a12 * mf1);
    float mp1 = fmaf(a21, mf0, a22 * mf1);
    float t00 = fmaf(a11, pf00, a12 * pf01);
    float t01 = fmaf(a11, pf01, a12 * pf11);
    float t10 = fmaf(a21, pf00, a22 * pf01);
    float t11 = fmaf(a21, pf01, a22 * pf11);
    float Pp00 = fmaf(t00, a11, fmaf(t01, a12, q00));
    float Pp01 = fmaf(t00, a21, fmaf(t01, a22, q01));
    float Pp11 = fmaf(t10, a21, fmaf(t11, a22, q11));
    float M00 = Pp00 + F_JITTER;
    float M11 = Pp11 + F_JITTER;
    float det = fmaf(M00, M11, -(Pp01 * Pp01));
    float di  = __fdividef(1.0f, det);
    float i00 =  M11 * di;
    float i01 = -Pp01 * di;
    float i11 =  M00 * di;
    g00 = fmaf(t00, i00, t10 * i01);
    g01 = fmaf(t00, i01, t10 * i11);
    g10 = fmaf(t01, i00, t11 * i01);
    g11 = fmaf(t01, i01, t11 * i11);
    h0 = mf0 - fmaf(g00, mp0, g01 * mp1);
    h1 = mf1 - fmaf(g10, mp0, g11 * mp1);
    float u00 = fmaf(g00, Pp00, g01 * Pp01);
    float u01 = fmaf(g00, Pp01, g01 * Pp11);
    float u10 = fmaf(g10, Pp00, g11 * Pp01);
    float u11 = fmaf(g10, Pp01, g11 * Pp11);
    W00 = pf00 + fmaf(u00, g00, u01 * g01);
    W01 = pf01 + fmaf(u00, g10, u01 * g11);
    W11 = pf11 + fmaf(u10, g10, u11 * g11);
}

// ---------------- filter element compose: E(earlier) (x) L(later) ----------------
__device__ __forceinline__ void fcompose(
    float &A00, float &A01, float &A10, float &A11,
    float &b0, float &b1, float &C00, float &C01, float &C11,
    float &e0, float &e1, float &J00, float &J01, float &J11,
    float lA00, float lA01, float lA10, float lA11,
    float lb0, float lb1, float lC00, float lC01, float lC11,
    float le0, float le1, float lJ00, float lJ01, float lJ11)
{
    float G00 = fmaf(C00, lJ00, fmaf(C01, lJ01, 1.0f));
    float G01 = fmaf(C00, lJ01, C01 * lJ11);
    float G10 = fmaf(C01, lJ00, C11 * lJ01);
    float G11 = fmaf(C01, lJ01, fmaf(C11, lJ11, 1.0f));
    float det = fmaf(G00, G11, -(G01 * G10));
    float id  = __fdividef(1.0f, det);
    float M00 =  G11 * id, M01 = -G01 * id, M10 = -G10 * id, M11 = G00 * id;
    float AM00 = fmaf(lA00, M00, lA01 * M10);
    float AM01 = fmaf(lA00, M01, lA01 * M11);
    float AM10 = fmaf(lA10, M00, lA11 * M10);
    float AM11 = fmaf(lA10, M01, lA11 * M11);
    float nA00 = fmaf(AM00, A00, AM01 * A10);
    float nA01 = fmaf(AM00, A01, AM01 * A11);
    float nA10 = fmaf(AM10, A00, AM11 * A10);
    float nA11 = fmaf(AM10, A01, AM11 * A11);
    float tb0 = fmaf(C00, le0, fmaf(C01, le1, b0));
    float tb1 = fmaf(C01, le0, fmaf(C11, le1, b1));
    float nb0 = fmaf(AM00, tb0, fmaf(AM01, tb1, lb0));
    float nb1 = fmaf(AM10, tb0, fmaf(AM11, tb1, lb1));
    float U00 = fmaf(AM00, C00, AM01 * C01);
    float U01 = fmaf(AM00, C01, AM01 * C11);
    float U10 = fmaf(AM10, C00, AM11 * C01);
    float U11 = fmaf(AM10, C01, AM11 * C11);
    float nC00 = fmaf(U00, lA00, fmaf(U01, lA01, lC00));
    float nC01 = fmaf(U00, lA10, fmaf(U01, lA11, lC01));
    float nC11 = fmaf(U10, lA10, fmaf(U11, lA11, lC11));
    float w0 = le0 - fmaf(lJ00, b0, lJ01 * b1);
    float w1 = le1 - fmaf(lJ01, b0, lJ11 * b1);
    float nw0 = fmaf(M00, w0, M10 * w1);
    float nw1 = fmaf(M01, w0, M11 * w1);
    float ne0 = fmaf(A00, nw0, fmaf(A10, nw1, e0));
    float ne1 = fmaf(A01, nw0, fmaf(A11, nw1, e1));
    float V00 = fmaf(M00, lJ00, M10 * lJ01);
    float V01 = fmaf(M00, lJ01, M10 * lJ11);
    float V10 = fmaf(M01, lJ00, M11 * lJ01);
    float V11 = fmaf(M01, lJ01, M11 * lJ11);
    float X00 = fmaf(A00, V00, A10 * V10);
    float X01 = fmaf(A00, V01, A10 * V11);
    float X10 = fmaf(A01, V00, A11 * V10);
    float X11 = fmaf(A01, V01, A11 * V11);
    float nJ00 = fmaf(X00, A00, fmaf(X01, A10, J00));
    float nJ01 = fmaf(X00, A01, fmaf(X01, A11, J01));
    float nJ11 = fmaf(X10, A01, fmaf(X11, A11, J11));
    A00=nA00; A01=nA01; A10=nA10; A11=nA11;
    b0=nb0; b1=nb1; C00=nC00; C01=nC01; C11=nC11;
    e0=ne0; e1=ne1; J00=nJ00; J01=nJ01; J11=nJ11;
}

// ---------------- filter element applied to a state ----------------
__device__ __forceinline__ void fapply(
    float &m0, float &m1, float &p0, float &p1, float &p2,
    float A00, float A01, float A10, float A11,
    float b0, float b1, float C00, float C01, float C11,
    float e0f, float e1f, float J00, float J01, float J11)
{
    float G00 = fmaf(p0, J00, fmaf(p1, J01, 1.0f));
    float G01 = fmaf(p0, J01, p1 * J11);
    float G10 = fmaf(p1, J00, p2 * J01);
    float G11 = fmaf(p1, J01, fmaf(p2, J11, 1.0f));
    float det = fmaf(G00, G11, -(G01 * G10));
    float id  = __fdividef(1.0f, det);
    float M00 =  G11 * id, M01 = -G01 * id, M10 = -G10 * id, M11 = G00 * id;
    float tb0 = fmaf(p0, e0f, fmaf(p1, e1f, m0));
    float tb1 = fmaf(p1, e0f, fmaf(p2, e1f, m1));
    float mt0 = fmaf(M00, tb0, M01 * tb1);
    float mt1 = fmaf(M10, tb0, M11 * tb1);
    float nm0 = fmaf(A00, mt0, fmaf(A01, mt1, b0));
    float nm1 = fmaf(A10, mt0, fmaf(A11, mt1, b1));
    float V00 = fmaf(M00, p0, M01 * p1);
    float V01 = fmaf(M00, p1, M01 * p2);
    float V10 = fmaf(M10, p0, M11 * p1);
    float V11 = fmaf(M10, p1, M11 * p2);
    float X00 = fmaf(A00, V00, A01 * V10);
    float X01 = fmaf(A00, V01, A01 * V11);
    float X10 = fmaf(A10, V00, A11 * V10);
    float X11 = fmaf(A10, V01, A11 * V11);
    float np0 = fmaf(X00, A00, fmaf(X01, A01, C00));
    float np1 = fmaf(X00, A10, fmaf(X01, A11, C01));
    float np2 = fmaf(X10, A10, fmaf(X11, A11, C11));
    m0 = nm0; m1 = nm1; p0 = np0; p1 = np1; p2 = np2;
}

// ---------------- smoother affine apply ----------------
__device__ __forceinline__ void sapply(
    float &m0, float &m1, float &p0, float &p1, float &p2,
    float4 sM, float4 sV, float4 s1, float4 s2, float2 s3)
{
    float nm0 = fmaf(sM.x, m0, fmaf(sM.y, m1, sV.x));
    float nm1 = fmaf(sM.z, m0, fmaf(sM.w, m1, sV.y));
    float np0 = fmaf(s1.x, p0, fmaf(s1.y, p1, fmaf(s1.z, p2, sV.z)));
    float np1 = fmaf(s1.w, p0, fmaf(s2.x, p1, fmaf(s2.y, p2, sV.w)));
    float np2 = fmaf(s2.z, p0, fmaf(s2.w, p1, fmaf(s3.x, p2, s3.y)));
    m0 = nm0; m1 = nm1; p0 = np0; p1 = np1; p2 = np2;
}

// ================= F2: filter chunk composites =================
__global__ void __launch_bounds__(512) fscan_chunk(
    const float* __restrict__ dtn,
    const float* __restrict__ ys,
    const float* __restrict__ rs,
    const float* __restrict__ ls,
    const float* __restrict__ vs)
{
    int c = threadIdx.x;
    int k = blockIdx.x;
    int v = c >> 4, l = c & 15;
    float lam = SQRT3 / ls[l];
    float s2  = vs[l];
    const float* yp = ys + (size_t)v * NT * NL + l;
    const float* rp = rs + (size_t)v * NT * NL + l;
    const float* dp = dtn + (size_t)v * NT1;

    float A00=1.f, A01=0.f, A10=0.f, A11=1.f;
    float b0=0.f, b1=0.f;
    float C00=0.f, C01=0.f, C11=0.f;
    float e0=0.f, e1=0.f;
    float J00=0.f, J01=0.f, J11=0.f;

    int tlo = (k == 0) ? 1 : CHF * k;
    int thi = CHF * k + CHF;
    for (int t = tlo; t < thi; ++t) {
        float dt = dp[t - 1];
        float y  = yp[(size_t)t * NL];
        float r  = rp[(size_t)t * NL];
        float a11,a12,a21,a22,q00,q01,q11;
        make_AQ(dt, lam, s2, a11,a12,a21,a22, q00,q01,q11);
        float S  = q00 + r;
        float iS = __fdividef(1.0f, S);
        float k0 = q00 * iS;
        float k1 = q01 * iS;
        float om = 1.0f - k0;
        float lA00 = om * a11, lA01 = om * a12;
        float lA10 = a21 - k1 * a11, lA11 = a22 - k1 * a12;
        float lb0 = k0 * y, lb1 = k1 * y;
        float lC00 = om * q00, lC01 = om * q01, lC11 = q11 - k1 * q01;
        float ySi = y * iS;
        float le0 = a11 * ySi, le1 = a12 * ySi;
        float lJ00 = a11 * a11 * iS, lJ01 = a11 * a12 * iS, lJ11 = a12 * a12 * iS;
        fcompose(A00,A01,A10,A11,b0,b1,C00,C01,C11,e0,e1,J00,J01,J11,
                 lA00,lA01,lA10,lA11,lb0,lb1,lC00,lC01,lC11,le0,le1,lJ00,lJ01,lJ11);
    }
    int ix = k * NC + c;
    g_feA[ix] = make_float4(A00, A01, A10, A11);
    g_feB[ix] = make_float4(b0, b1, e0, e1);
    g_feC[ix] = make_float4(C00, C01, C11, J00);
    g_feJ[ix] = make_float2(J01, J11);
}

// ================= F2b: compose 16 chunks -> super composites =================
__global__ void __launch_bounds__(512) fcarry1()
{
    int c = threadIdx.x;
    int s = blockIdx.x;
    float A00=1.f, A01=0.f, A10=0.f, A11=1.f;
    float b0=0.f, b1=0.f, C00=0.f, C01=0.f, C11=0.f;
    float e0=0.f, e1=0.f, J00=0.f, J01=0.f, J11=0.f;
    int base = (s * 16) * NC + c;
    float4 fA = g_feA[base], fB = g_feB[base], fC = g_feC[base];
    float2 fJ = g_feJ[base];
    #pragma unroll
    for (int j = 0; j < 16; ++j) {
        float4 pA, pB, pC; float2 pJ;
        if (j < 15) {
            int nx = base + (j + 1) * NC;
            pA = g_feA[nx]; pB = g_feB[nx]; pC = g_feC[nx]; pJ = g_feJ[nx];
        }
        fcompose(A00,A01,A10,A11,b0,b1,C00,C01,C11,e0,e1,J00,J01,J11,
                 fA.x,fA.y,fA.z,fA.w, fB.x,fB.y, fC.x,fC.y,fC.z,
                 fB.z,fB.w, fC.w,fJ.x,fJ.y);
        fA = pA; fB = pB; fC = pC; fJ = pJ;
    }
    int ox = s * NC + c;
    g_sfA[ox] = make_float4(A00, A01, A10, A11);
    g_sfB[ox] = make_float4(b0, b1, e0, e1);
    g_sfC[ox] = make_float4(C00, C01, C11, J00);
    g_sfJ[ox] = make_float2(J01, J11);
}

// ================= F3a: serial scan over 16 supers =================
__global__ void __launch_bounds__(512) fcarry2(
    const float* __restrict__ ys,
    const float* __restrict__ rs,
    const float* __restrict__ ls,
    const float* __restrict__ vs)
{
    int c = threadIdx.x;
    int v = c >> 4, l = c & 15;
    float lam = SQRT3 / ls[l];
    float s2  = vs[l];
    float y0 = ys[(size_t)v * NT * NL + l];
    float r0 = rs[(size_t)v * NT * NL + l];
    float s  = s2 + r0;
    float inv = __fdividef(1.0f, s + F_JITTER);
    float w0 = s2 * inv;
    float m0 = w0 * y0, m1 = 0.0f;
    float p0 = s2 - w0 * s2, p1 = 0.0f, p2 = s2 * lam * lam;

    float4 fA = g_sfA[c], fB = g_sfB[c], fC = g_sfC[c];
    float2 fJ = g_sfJ[c];
    #pragma unroll
    for (int ss = 0; ss < NSF; ++ss) {
        float4 pA, pB, pC; float2 pJ;
        if (ss < NSF - 1) {
            int nx = (ss + 1) * NC + c;
            pA = g_sfA[nx]; pB = g_sfB[nx]; pC = g_sfC[nx]; pJ = g_sfJ[nx];
        }
        int ix = ss * NC + c;
        g_fbM2[ix] = make_float2(m0, m1);
        g_fbP2[ix] = make_float4(p0, p1, p2, 0.0f);
        fapply(m0,m1,p0,p1,p2,
               fA.x,fA.y,fA.z,fA.w, fB.x,fB.y, fC.x,fC.y,fC.z,
               fB.z,fB.w, fC.w,fJ.x,fJ.y);
        fA = pA; fB = pB; fC = pC; fJ = pJ;
    }
    // state is now filtered at t = NT-1
    g_ffM[c] = make_float2(m0, m1);
    g_ffP[c] = make_float4(p0, p1, p2, 0.0f);
}

// ================= F3b: expand super -> chunk boundaries =================
__global__ void __launch_bounds__(512) fcarry3()
{
    int c = threadIdx.x;
    int s = blockIdx.x;
    float2 bm = g_fbM2[s * NC + c];
    float4 bp = g_fbP2[s * NC + c];
    float m0 = bm.x, m1 = bm.y, p0 = bp.x, p1 = bp.y, p2 = bp.z;
    int base = (s * 16) * NC + c;
    float4 fA = g_feA[base], fB = g_feB[base], fC = g_feC[base];
    float2 fJ = g_feJ[base];
    #pragma unroll
    for (int j = 0; j < 16; ++j) {
        float4 pA, pB, pC; float2 pJ;
        if (j < 15) {
            int nx = base + (j + 1) * NC;
            pA = g_feA[nx]; pB = g_feB[nx]; pC = g_feC[nx]; pJ = g_feJ[nx];
        }
        int ix = base + j * NC;
        g_fbM[ix] = make_float2(m0, m1);
        g_fbP[ix] = make_float4(p0, p1, p2, 0.0f);
        fapply(m0,m1,p0,p1,p2,
               fA.x,fA.y,fA.z,fA.w, fB.x,fB.y, fC.x,fC.y,fC.z,
               fB.z,fB.w, fC.w,fJ.x,fJ.y);
        fA = pA; fB = pB; fC = pC; fJ = pJ;
    }
}

// ================= F4/S2 fused: re-filter + build smoother composites =================
__global__ void __launch_bounds__(512) fsmcomp(
    const float* __restrict__ dtn,
    const float* __restrict__ ys,
    const float* __restrict__ rs,
    const float* __restrict__ ls,
    const float* __restrict__ vs)
{
    int c = threadIdx.x;
    int k = blockIdx.x;
    int v = c >> 4, l = c & 15;
    float lam = SQRT3 / ls[l];
    float s2  = vs[l];
    const float* yp = ys + (size_t)v * NT * NL + l;
    const float* rp = rs + (size_t)v * NT * NL + l;
    const float* dp = dtn + (size_t)v * NT1;

    // smoother composite accumulator (identity)
    float M00=1.f, M01=0.f, M10=0.f, M11=1.f, v0=0.f, v1=0.f;
    float L00=1.f, L01=0.f, L02=0.f;
    float L10=0.f, L11=1.f, L12=0.f;
    float L20=0.f, L21=0.f, L22=1.f;
    float w0=0.f, w1=0.f, w2=0.f;

    float m0, m1, p0, p1, p2;
    float a11,a12,a21,a22,q00,q01,q11;  // AQ for dt[t-1] (carried)

#define RCOMPOSE() { \
    float g00,g01,g10,g11,h0,h1,W00,W01,W11; \
    sgain(m0, m1, p0, p1, p2, a11,a12,a21,a22, q00,q01,q11, \
          g00,g01,g10,g11, h0,h1, W00,W01,W11); \
    float T00 = g00*g00, T01 = 2.0f*g00*g01, T02 = g01*g01; \
    float T10 = g00*g10, T11 = fmaf(g00,g11, g01*g10), T12 = g01*g11; \
    float T20 = g10*g10, T21 = 2.0f*g10*g11, T22 = g11*g11; \
    float nM00 = fmaf(M00, g00, M01 * g10); \
    float nM01 = fmaf(M00, g01, M01 * g11); \
    float nM10 = fmaf(M10, g00, M11 * g10); \
    float nM11 = fmaf(M10, g01, M11 * g11); \
    float nv0 = fmaf(M00, h0, fmaf(M01, h1, v0)); \
    float nv1 = fmaf(M10, h0, fmaf(M11, h1, v1)); \
    float nL00 = -fmaf(L00, T00, fmaf(L01, T10, L02 * T20)); \
    float nL01 = -fmaf(L00, T01, fmaf(L01, T11, L02 * T21)); \
    float nL02 = -fmaf(L00, T02, fmaf(L01, T12, L02 * T22)); \
    float nL10 = -fmaf(L10, T00, fmaf(L11, T10, L12 * T20)); \
    float nL11 = -fmaf(L10, T01, fmaf(L11, T11, L12 * T21)); \
    float nL12 = -fmaf(L10, T02, fmaf(L11, T12, L12 * T22)); \
    float nL20 = -fmaf(L20, T00, fmaf(L21, T10, L22 * T20)); \
    float nL21 = -fmaf(L20, T01, fmaf(L21, T11, L22 * T21)); \
    float nL22 = -fmaf(L20, T02, fmaf(L21, T12, L22 * T22)); \
    float nw0 = fmaf(L00, W00, fmaf(L01, W01, fmaf(L02, W11, w0))); \
    float nw1 = fmaf(L10, W00, fmaf(L11, W01, fmaf(L12, W11, w1))); \
    float nw2 = fmaf(L20, W00, fmaf(L21, W01, fmaf(L22, W11, w2))); \
    M00=nM00; M01=nM01; M10=nM10; M11=nM11; v0=nv0; v1=nv1; \
    L00=nL00; L01=nL01; L02=nL02; L10=nL10; L11=nL11; L12=nL12; \
    L20=nL20; L21=nL21; L22=nL22; w0=nw0; w1=nw1; w2=nw2; }

    int tlo;
    if (k == 0) {
        float y = yp[0], r = rp[0];
        float s = s2 + r;
        float inv = __fdividef(1.0f, s + F_JITTER);
        float wk = s2 * inv;
        m0 = wk * y; m1 = 0.0f;
        p0 = s2 - wk * s2; p1 = 0.0f; p2 = s2 * lam * lam;
        // elem at t=0 (dt = dp[0])
        make_AQ(dp[0], lam, s2, a11,a12,a21,a22, q00,q01,q11);
        RCOMPOSE();
        tlo = 1;
    } else {
        float2 bm = g_fbM[k * NC + c];
        float4 bp = g_fbP[k * NC + c];
        m0 = bm.x; m1 = bm.y; p0 = bp.x; p1 = bp.y; p2 = bp.z;
        make_AQ(dp[CHF*k - 1], lam, s2, a11,a12,a21,a22, q00,q01,q11);
        tlo = CHF * k;
    }
    int thi = (k == NKF - 1) ? (NT - 1) : (CHF * k + CHF);   // exclusive
    for (int t = tlo; t < thi; ++t) {
        float y = yp[(size_t)t * NL];
        float r = rp[(size_t)t * NL];
        fstep(m0, m1, p0, p1, p2, a11,a12,a21,a22, q00,q01,q11, y, r);
        // elem at t uses dt = dp[t]
        make_AQ(dp[t], lam, s2, a11,a12,a21,a22, q00,q01,q11);
        RCOMPOSE();
    }
#undef RCOMPOSE
    int ix = k * NC + c;
    g_seM[ix]  = make_float4(M00, M01, M10, M11);
    g_seV[ix]  = make_float4(v0, v1, w0, w1);
    g_seL1[ix] = make_float4(L00, L01, L02, L10);
    g_seL2[ix] = make_float4(L11, L12, L20, L21);
    g_seL3[ix] = make_float2(L22, w2);
}

// ================= S2b: compose 16 smoother chunks -> super =================
__global__ void __launch_bounds__(512) scarry1()
{
    int c = threadIdx.x;
    int s = blockIdx.x;
    float M00=1.f, M01=0.f, M10=0.f, M11=1.f, v0=0.f, v1=0.f;
    float L00=1.f, L01=0.f, L02=0.f;
    float L10=0.f, L11=1.f, L12=0.f;
    float L20=0.f, L21=0.f, L22=1.f;
    float w0=0.f, w1=0.f, w2=0.f;
    int base = s * 16 * NC + c;
    float4 eM = g_seM[base + 15*NC], eV = g_seV[base + 15*NC];
    float4 e1 = g_seL1[base + 15*NC], e2 = g_seL2[base + 15*NC];
    float2 e3 = g_seL3[base + 15*NC];
    #pragma unroll
    for (int j = 15; j >= 0; --j) {
        float4 pM, pV, p1, p2; float2 p3;
        if (j > 0) {
            int nx = base + (j - 1) * NC;
            pM = g_seM[nx]; pV = g_seV[nx]; p1 = g_seL1[nx]; p2 = g_seL2[nx]; p3 = g_seL3[nx];
        }
        // comp <- elem_j o comp
        float nM00 = fmaf(eM.x, M00, eM.y * M10);
        float nM01 = fmaf(eM.x, M01, eM.y * M11);
        float nM10 = fmaf(eM.z, M00, eM.w * M10);
        float nM11 = fmaf(eM.z, M01, eM.w * M11);
        float nv0 = fmaf(eM.x, v0, fmaf(eM.y, v1, eV.x));
        float nv1 = fmaf(eM.z, v0, fmaf(eM.w, v1, eV.y));
        float E00=e1.x, E01=e1.y, E02=e1.z, E10=e1.w, E11=e2.x, E12=e2.y;
        float E20=e2.z, E21=e2.w, E22=e3.x;
        float a0 = fmaf(E00, L00, fmaf(E01, L10, E02 * L20));
        float a1 = fmaf(E00, L01, fmaf(E01, L11, E02 * L21));
        float a2 = fmaf(E00, L02, fmaf(E01, L12, E02 * L22));
        float bb0 = fmaf(E10, L00, fmaf(E11, L10, E12 * L20));
        float bb1 = fmaf(E10, L01, fmaf(E11, L11, E12 * L21));
        float bb2 = fmaf(E10, L02, fmaf(E11, L12, E12 * L22));
        float cc0 = fmaf(E20, L00, fmaf(E21, L10, E22 * L20));
        float cc1 = fmaf(E20, L01, fmaf(E21, L11, E22 * L21));
        float cc2 = fmaf(E20, L02, fmaf(E21, L12, E22 * L22));
        float nw0 = fmaf(E00, w0, fmaf(E01, w1, fmaf(E02, w2, eV.z)));
        float nw1 = fmaf(E10, w0, fmaf(E11, w1, fmaf(E12, w2, eV.w)));
        float nw2 = fmaf(E20, w0, fmaf(E21, w1, fmaf(E22, w2, e3.y)));
        M00=nM00; M01=nM01; M10=nM10; M11=nM11; v0=nv0; v1=nv1;
        L00=a0; L01=a1; L02=a2; L10=bb0; L11=bb1; L12=bb2; L20=cc0; L21=cc1; L22=cc2;
        w0=nw0; w1=nw1; w2=nw2;
        eM = pM; eV = pV; e1 = p1; e2 = p2; e3 = p3;
    }
    int ox = s * NC + c;
    g_ssM[ox]  = make_float4(M00, M01, M10, M11);
    g_ssV[ox]  = make_float4(v0, v1, w0, w1);
    g_ssL1[ox] = make_float4(L00, L01, L02, L10);
    g_ssL2[ox] = make_float4(L11, L12, L20, L21);
    g_ssL3[ox] = make_float2(L22, w2);
}

// ================= S3a: serial scan over 16 supers (backward) =================
__global__ void __launch_bounds__(512) scarry2()
{
    int c = threadIdx.x;
    float2 fm = g_ffM[c];
    float4 fp = g_ffP[c];
    float m0 = fm.x, m1 = fm.y;
    float p0 = fp.x, p1 = fp.y, p2 = fp.z;
    #pragma unroll
    for (int s = NSF - 1; s >= 0; --s) {
        int ix = s * NC + c;
        g_sbM2[ix] = make_float2(m0, m1);
        g_sbP2[ix] = make_float4(p0, p1, p2, 0.0f);
        sapply(m0, m1, p0, p1, p2,
               g_ssM[ix], g_ssV[ix], g_ssL1[ix], g_ssL2[ix], g_ssL3[ix]);
    }
}

// ================= S3b: expand super -> chunk boundaries =================
__global__ void __launch_bounds__(512) scarry3()
{
    int c = threadIdx.x;
    int s = blockIdx.x;
    float2 bm = g_sbM2[s * NC + c];
    float4 bp = g_sbP2[s * NC + c];
    float m0 = bm.x, m1 = bm.y, p0 = bp.x, p1 = bp.y, p2 = bp.z;
    int base = s * 16 * NC + c;
    float4 eM = g_seM[base + 15*NC], eV = g_seV[base + 15*NC];
    float4 e1 = g_seL1[base + 15*NC], e2 = g_seL2[base + 15*NC];
    float2 e3 = g_seL3[base + 15*NC];
    #pragma unroll
    for (int j = 15; j >= 0; --j) {
        float4 pM, pV, p1v, p2v; float2 p3v;
        if (j > 0) {
            int nx = base + (j - 1) * NC;
            pM = g_seM[nx]; pV = g_seV[nx]; p1v = g_seL1[nx]; p2v = g_seL2[nx]; p3v = g_seL3[nx];
        }
        int ix = base + j * NC;
        g_sbM[ix] = make_float2(m0, m1);
        g_sbP[ix] = make_float4(p0, p1, p2, 0.0f);
        sapply(m0, m1, p0, p1, p2, eM, eV, e1, e2, e3);
        eM = pM; eV = pV; e1 = p1v; e2 = p2v; e3 = p3v;
    }
}

// ================= SOLVE: re-filter + re-smooth + direct outputs =================
// grid (NKF, 4), block 128, dynamic smem = SOLVE_SMEM
__global__ void __launch_bounds__(128) solve_kernel(
    const float* __restrict__ dtn,
    const float* __restrict__ ys,
    const float* __restrict__ rs,
    const float* __restrict__ ls,
    const float* __restrict__ vs,
    float* __restrict__ out)
{
    extern __shared__ char sh[];
    float2* sm = (float2*)sh;                   // [128][33] swizzled
    float4* sp = (float4*)(sh + 128 * 33 * 8);  // [128][33] swizzled
#define SM(ch, tl) sm[(ch) * 33 + ((tl) ^ (((ch) >> 4) & 1))]
#define SP(ch, tl) sp[(ch) * 33 + ((tl) ^ (((ch) >> 3) & 7))]

    int tid = threadIdx.x;
    int k = blockIdx.x;
    int cbase = blockIdx.y * 128;
    int c = cbase + tid;
    int v = c >> 4, l = c & 15;
    float lam = SQRT3 / ls[l];
    float s2  = vs[l];
    const float* yp = ys + (size_t)v * NT * NL + l;
    const float* rp = rs + (size_t)v * NT * NL + l;
    const float* dp = dtn + (size_t)v * NT1;
    int t0 = CHF * k;

    // ---- forward: exact filter over chunk, fill smem tile ----
    float m0, m1, p0, p1, p2;
    float acc = 0.0f;
    int tlo;
    if (k == 0) {
        float y = yp[0], r = rp[0];
        float s = s2 + r;
        float inv = __fdividef(1.0f, s + F_JITTER);
        float w0 = s2 * inv;
        m0 = w0 * y; m1 = 0.0f;
        p0 = s2 - w0 * s2; p1 = 0.0f; p2 = s2 * lam * lam;
        acc = fmaf(y * y, inv, __logf(s));
        SM(tid, 0) = make_float2(m0, m1);
        SP(tid, 0) = make_float4(p0, p1, p1, p2);
        tlo = 1;
    } else {
        float2 bm = g_fbM[k * NC + c];
        float4 bp = g_fbP[k * NC + c];
        m0 = bm.x; m1 = bm.y; p0 = bp.x; p1 = bp.y; p2 = bp.z;
        tlo = t0;
    }
    for (int t = tlo; t < t0 + CHF; ++t) {
        float a11,a12,a21,a22,q00,q01,q11;
        make_AQ(dp[t - 1], lam, s2, a11,a12,a21,a22, q00,q01,q11);
        acc += fstep(m0, m1, p0, p1, p2, a11,a12,a21,a22, q00,q01,q11,
                     yp[(size_t)t * NL], rp[(size_t)t * NL]);
        int tl = t - t0;
        SM(tid, tl) = make_float2(m0, m1);
        SP(tid, tl) = make_float4(p0, p1, p1, p2);
    }
    g_lpp[k * NC + c] = acc;
    __syncthreads();

    // ---- bulk write filtered m, P to output (coalesced) ----
    {
        float2* om = (float2*)out;
        int sub = tid & 3, grp = tid >> 2;
        #pragma unroll
        for (int rep = 0; rep < 4; ++rep) {
            int ch = rep * 32 + grp;
            size_t rowb = (size_t)(cbase + ch) * NT + t0;
            #pragma unroll
            for (int it = 0; it < 8; ++it) {
                int tl = it * 4 + sub;
                om[rowb + tl] = SM(ch, tl);
            }
        }
        float4* op = (float4*)(out + OFF_P);
        int sub8 = tid & 7, grp8 = tid >> 3;
        #pragma unroll
        for (int rep = 0; rep < 8; ++rep) {
            int ch = rep * 16 + grp8;
            size_t rowb = (size_t)(cbase + ch) * NT + t0;
            #pragma unroll
            for (int it = 0; it < 4; ++it) {
                int tl = it * 8 + sub8;
                op[rowb + tl] = SP(ch, tl);
            }
        }
    }
    __syncthreads();

    // ---- backward: smooth in place (overwrite SM slots with (mz, pz)) ----
    {
        float2 bm = g_sbM[k * NC + c];
        float4 bp = g_sbP[k * NC + c];
        float ms0 = bm.x, ms1 = bm.y;
        float s00 = bp.x, s01 = bp.y, s11 = bp.z;
        int tstart;
        if (k == NKF - 1) {
            // slot 31 (t = NT-1): smoothed == filtered (regs hold filtered @ NT-1)
            SM(tid, CHF - 1) = make_float2(m0, p0);
            tstart = NT - 2;
        } else {
            tstart = t0 + CHF - 1;
        }
        for (int t = tstart; t >= t0; --t) {
            int tl = t - t0;
            float2 mf = SM(tid, tl);
            float4 pf = SP(tid, tl);
            float a11,a12,a21,a22,q00,q01,q11;
            make_AQ(dp[t], lam, s2, a11,a12,a21,a22, q00,q01,q11);
            float g00,g01,g10,g11,h0,h1,W00,W01,W11;
            sgain(mf.x, mf.y, pf.x, pf.y, pf.w, a11,a12,a21,a22, q00,q01,q11,
                  g00,g01,g10,g11, h0,h1, W00,W01,W11);
            float u00 = fmaf(g00, s00, g01 * s01);
            float u01 = fmaf(g00, s01, g01 * s11);
            float u10 = fmaf(g10, s00, g11 * s01);
            float u11 = fmaf(g10, s01, g11 * s11);
            float nm0 = fmaf(g00, ms0, fmaf(g01, ms1, h0));
            float nm1 = fmaf(g10, ms0, fmaf(g11, ms1, h1));
            s00 = W00 - fmaf(u00, g00, u01 * g01);
            s01 = W01 - fmaf(u00, g10, u01 * g11);
            s11 = W11 - fmaf(u10, g10, u11 * g11);
            ms0 = nm0; ms1 = nm1;
            SM(tid, tl) = make_float2(ms0, s00);
        }
    }
    __syncthreads();

    // ---- bulk write mz, pz (coalesced float4) ----
    {
        float* omz = out + OFF_MZ;
        float* opz = out + OFF_PZ;
        int sub = tid & 1, grp = tid >> 1;
        #pragma unroll
        for (int rep = 0; rep < 2; ++rep) {
            int ch = rep * 64 + grp;
            size_t rowb = (size_t)(cbase + ch) * NT + t0;
            #pragma unroll
            for (int it = 0; it < 4; ++it) {
                int f4 = it * 2 + sub;
                float2 e0 = SM(ch, f4 * 4 + 0);
                float2 e1 = SM(ch, f4 * 4 + 1);
                float2 e2 = SM(ch, f4 * 4 + 2);
                float2 e3 = SM(ch, f4 * 4 + 3);
                ((float4*)(omz + rowb))[f4] = make_float4(e0.x, e1.x, e2.x, e3.x);
                ((float4*)(opz + rowb))[f4] = make_float4(e0.y, e1.y, e2.y, e3.y);
            }
        }
    }
#undef SM
#undef SP
}

// ---------------- deterministic log-lik reduction ----------------
__global__ void __launch_bounds__(512) logp_kernel(float* __restrict__ out)
{
    __shared__ double sh[NC];
    int c = threadIdx.x;
    double a = 0.0;
    for (int k = 0; k < NKF; ++k) a += (double)g_lpp[k * NC + c];
    sh[c] = -0.5 * (a + (double)NT * (double)F_LOG2PI);
    __syncthreads();
    if (c < NV) {
        double s = 0.0;
        #pragma unroll
        for (int l = 0; l < NL; ++l) s += sh[c * NL + l];
        out[OFF_LP + c] = (float)s;
    }
}

extern "C" void kernel_launch(void* const* d_in, const int* in_sizes, int n_in,
                              void* d_out, int out_size)
{
    const float* dtn = (const float*)d_in[0];
    const float* ys  = (const float*)d_in[1];
    const float* rs  = (const float*)d_in[2];
    const float* ls  = (const float*)d_in[3];
    const float* vs  = (const float*)d_in[4];
    float* out = (float*)d_out;

    cudaFuncSetAttribute(solve_kernel,
                         cudaFuncAttributeMaxDynamicSharedMemorySize, SOLVE_SMEM);

    fscan_chunk<<<NKF, 512>>>(dtn, ys, rs, ls, vs);
    fcarry1<<<NSF, 512>>>();
    fcarry2<<<1, 512>>>(ys, rs, ls, vs);
    fcarry3<<<NSF, 512>>>();
    fsmcomp<<<NKF, 512>>>(dtn, ys, rs, ls, vs);
    scarry1<<<NSF, 512>>>();
    scarry2<<<1, 512>>>();
    scarry3<<<NSF, 512>>>();
    solve_kernel<<<dim3(NKF, 4), 128, SOLVE_SMEM>>>(dtn, ys, rs, ls, vs, out);
    logp_kernel<<<1, 512>>>(out);
}